// round 11
// baseline (speedup 1.0000x reference)
#include <cuda_runtime.h>
#include <cuda_bf16.h>
#include <cuda_fp16.h>
#include <math.h>
#include <stdint.h>

#define DD 128
#define SS 4096
#define BB 4

__device__ __nv_bfloat16 g_Qh[BB * SS * DD];
__device__ __nv_bfloat16 g_Ql[BB * SS * DD];
__device__ __nv_bfloat16 g_Kh[BB * SS * DD];
__device__ __nv_bfloat16 g_Kl[BB * SS * DD];
__device__ __nv_bfloat16 g_Vth[BB * DD * SS];   // [b*128+d][token]
__device__ __nv_bfloat16 g_Vtl[BB * DD * SS];
__device__ float g_rq[BB * SS];
__device__ float g_rk[BB * SS];

// ---- PTX helpers (arch-portable) ----
__device__ __forceinline__ uint32_t smem_u32(const void* p) {
    uint32_t a;
    asm("{ .reg .u64 t; cvta.to.shared.u64 t, %1; cvt.u32.u64 %0, t; }" : "=r"(a) : "l"(p));
    return a;
}
__device__ __forceinline__ void ldsm4(uint32_t* d, uint32_t addr) {
    asm volatile("ldmatrix.sync.aligned.m8n8.x4.shared.b16 {%0,%1,%2,%3}, [%4];"
                 : "=r"(d[0]), "=r"(d[1]), "=r"(d[2]), "=r"(d[3]) : "r"(addr));
}
__device__ __forceinline__ void mma16816(float* c, const uint32_t* a, const uint32_t* b) {
    asm volatile("mma.sync.aligned.m16n8k16.row.col.f32.bf16.bf16.f32 "
                 "{%0,%1,%2,%3}, {%4,%5,%6,%7}, {%8,%9}, {%0,%1,%2,%3};"
                 : "+f"(c[0]), "+f"(c[1]), "+f"(c[2]), "+f"(c[3])
                 : "r"(a[0]), "r"(a[1]), "r"(a[2]), "r"(a[3]), "r"(b[0]), "r"(b[1]));
}
__device__ __forceinline__ void mma16816h(float* c, const uint32_t* a, const uint32_t* b) {
    asm volatile("mma.sync.aligned.m16n8k16.row.col.f32.f16.f16.f32 "
                 "{%0,%1,%2,%3}, {%4,%5,%6,%7}, {%8,%9}, {%0,%1,%2,%3};"
                 : "+f"(c[0]), "+f"(c[1]), "+f"(c[2]), "+f"(c[3])
                 : "r"(a[0]), "r"(a[1]), "r"(a[2]), "r"(a[3]), "r"(b[0]), "r"(b[1]));
}
__device__ __forceinline__ uint32_t pack_bf16x2(float lo, float hi) {
    uint32_t r;
    asm("cvt.rn.bf16x2.f32 %0, %1, %2;" : "=r"(r) : "f"(hi), "f"(lo));
    return r;
}
__device__ __forceinline__ void cpasync16(uint32_t s, const void* g) {
    asm volatile("cp.async.cg.shared.global [%0], [%1], 16;" :: "r"(s), "l"(g));
}
#define CP_COMMIT() asm volatile("cp.async.commit_group;" ::: "memory")
#define CP_WAIT0()  asm volatile("cp.async.wait_group 0;" ::: "memory")
#define CP_WAIT1()  asm volatile("cp.async.wait_group 1;" ::: "memory")

__device__ __forceinline__ uint32_t sw256(int r, int c16) {   // 256B rows
    return (uint32_t)(r * 256 + (((c16 & 8) | ((c16 & 7) ^ (r & 7))) << 4));
}
__device__ __forceinline__ uint32_t sw64(int r, int c4) {     // 64B rows (32 bf16)
    return (uint32_t)(r * 64 + (((c4 + (r >> 1)) & 3) << 4));
}

// ================= fused QKV projection + center/split/transpose =============
#define PA_H 0
#define PA_L 32768
#define PB_H 65536
#define PB_L 98304
#define PC_OFF 131072
#define PR_OFF (PC_OFF + 128 * 132 * 4)
#define PSMEM  (PR_OFF + 1024)

__global__ __launch_bounds__(256, 1) void proj_kernel(const float* __restrict__ xg,
                                                      const float* __restrict__ wq,
                                                      const float* __restrict__ wk,
                                                      const float* __restrict__ wv) {
    extern __shared__ char smem[];
    const uint32_t sb = smem_u32(smem);
    float* tileC = (float*)(smem + PC_OFF);
    float* rmean = (float*)(smem + PR_OFF);
    const int t = threadIdx.x, w = t >> 5, lane = t & 31;
    const int tile = blockIdx.x, proj = blockIdx.y;
    const int tok0 = tile * 128;
    const int b = tok0 >> 12, s0 = tok0 & (SS - 1);
    const float* W = (proj == 0) ? wq : (proj == 1) ? wk : wv;
    const float SCALE = 0.08838834764831845f;

    #pragma unroll
    for (int it = 0; it < 8; it++) {
        int lin = t + it * 256;
        int r = lin >> 4, c16 = lin & 15;
        const float* src = xg + (size_t)(tok0 + r) * DD + c16 * 8;
        float4 v0 = *reinterpret_cast<const float4*>(src);
        float4 v1 = *reinterpret_cast<const float4*>(src + 4);
        __half2 h0 = __floats2half2_rn(v0.x, v0.y), h1 = __floats2half2_rn(v0.z, v0.w);
        __half2 h2 = __floats2half2_rn(v1.x, v1.y), h3 = __floats2half2_rn(v1.z, v1.w);
        float2 f0 = __half22float2(h0), f1 = __half22float2(h1);
        float2 f2 = __half22float2(h2), f3 = __half22float2(h3);
        __half2 l0 = __floats2half2_rn(v0.x - f0.x, v0.y - f0.y);
        __half2 l1 = __floats2half2_rn(v0.z - f1.x, v0.w - f1.y);
        __half2 l2 = __floats2half2_rn(v1.x - f2.x, v1.y - f2.y);
        __half2 l3 = __floats2half2_rn(v1.z - f3.x, v1.w - f3.y);
        uint4 hv = make_uint4(*(uint32_t*)&h0, *(uint32_t*)&h1, *(uint32_t*)&h2, *(uint32_t*)&h3);
        uint4 lv = make_uint4(*(uint32_t*)&l0, *(uint32_t*)&l1, *(uint32_t*)&l2, *(uint32_t*)&l3);
        *reinterpret_cast<uint4*>(smem + PA_H + sw256(r, c16)) = hv;
        *reinterpret_cast<uint4*>(smem + PA_L + sw256(r, c16)) = lv;
    }
    #pragma unroll
    for (int it = 0; it < 8; it++) {
        int lin = t + it * 256;
        int d = lin >> 4, c16 = lin & 15;
        const float* src = W + (size_t)d * DD + c16 * 8;
        float wv[8];
        *reinterpret_cast<float4*>(wv) = *reinterpret_cast<const float4*>(src);
        *reinterpret_cast<float4*>(wv + 4) = *reinterpret_cast<const float4*>(src + 4);
        #pragma unroll
        for (int j = 0; j < 8; j++) {
            int e = c16 * 8 + j;
            __half h = __float2half_rn(wv[j]);
            __half l = __float2half_rn(wv[j] - __half2float(h));
            uint32_t off = sw256(e, d >> 3) + (d & 7) * 2;
            *reinterpret_cast<__half*>(smem + PB_H + off) = h;
            *reinterpret_cast<__half*>(smem + PB_L + off) = l;
        }
    }
    __syncthreads();

    const int m0 = w * 16;
    const int g = lane >> 3, rr = lane & 7;
    const int rowA = m0 + ((g & 1) << 3) + rr;  const int hA = g >> 1;
    const int rowB8 = ((g >> 1) << 3) + rr;      const int hB = g & 1;

    float C[16][4];
    #pragma unroll
    for (int i = 0; i < 16; i++) { C[i][0] = C[i][1] = C[i][2] = C[i][3] = 0.f; }
    #pragma unroll
    for (int kc = 0; kc < 8; kc++) {
        uint32_t Ah[4], Al[4];
        ldsm4(Ah, sb + PA_H + sw256(rowA, kc * 2 + hA));
        ldsm4(Al, sb + PA_L + sw256(rowA, kc * 2 + hA));
        #pragma unroll
        for (int np = 0; np < 8; np++) {
            uint32_t Bh[4], Bl[4];
            ldsm4(Bh, sb + PB_H + sw256(np * 16 + rowB8, kc * 2 + hB));
            ldsm4(Bl, sb + PB_L + sw256(np * 16 + rowB8, kc * 2 + hB));
            mma16816h(C[2 * np], Ah, Bh);     mma16816h(C[2 * np + 1], Ah, Bh + 2);
            mma16816h(C[2 * np], Ah, Bl);     mma16816h(C[2 * np + 1], Ah, Bl + 2);
            mma16816h(C[2 * np], Al, Bh);     mma16816h(C[2 * np + 1], Al, Bh + 2);
        }
    }
    __syncthreads();

    const int lr = lane >> 2, lc = 2 * (lane & 3);
    #pragma unroll
    for (int np = 0; np < 8; np++) {
        #pragma unroll
        for (int nn = 0; nn < 2; nn++) {
            int c0 = np * 16 + nn * 8 + lc;
            float* p0 = tileC + (m0 + lr) * 132 + c0;
            float* p1 = tileC + (m0 + lr + 8) * 132 + c0;
            p0[0] = C[np * 2 + nn][0]; p0[1] = C[np * 2 + nn][1];
            p1[0] = C[np * 2 + nn][2]; p1[1] = C[np * 2 + nn][3];
        }
    }
    __syncthreads();

    if (proj < 2) {
        const int r = t >> 1, part = t & 1;
        float s = 0.f;
        #pragma unroll
        for (int j = 0; j < 16; j++) {
            float4 v = *reinterpret_cast<float4*>(tileC + r * 132 + part * 64 + j * 4);
            s += v.x + v.y + v.z + v.w;
        }
        s += __shfl_xor_sync(0xFFFFFFFFu, s, 1);
        if (proj == 0) {
            float rq = s * SCALE;
            if (part == 0) { rmean[r] = rq * (1.f / 128.f); g_rq[tok0 + r] = rq; }
        } else {
            float mk = s * (1.f / 128.f);
            if (part == 0) { rmean[r] = mk; g_rk[tok0 + r] = mk; }
        }
        __syncthreads();
        const float mu = rmean[r];
        __nv_bfloat16* gh = (proj == 0) ? g_Qh : g_Kh;
        __nv_bfloat16* gl = (proj == 0) ? g_Ql : g_Kl;
        const float fac = (proj == 0) ? SCALE : 1.f;
        #pragma unroll
        for (int j8 = 0; j8 < 8; j8++) {
            int c = part * 64 + j8 * 8;
            __align__(16) __nv_bfloat16 hs[8], ls[8];
            #pragma unroll
            for (int j = 0; j < 8; j++) {
                float v = tileC[r * 132 + c + j] * fac - mu;
                __nv_bfloat16 h = __float2bfloat16(v);
                hs[j] = h; ls[j] = __float2bfloat16(v - __bfloat162float(h));
            }
            size_t ob = (size_t)(tok0 + r) * DD + c;
            *reinterpret_cast<uint4*>(&gh[ob]) = *reinterpret_cast<uint4*>(hs);
            *reinterpret_cast<uint4*>(&gl[ob]) = *reinterpret_cast<uint4*>(ls);
        }
    } else {
        const int od = t >> 1, seg = t & 1;
        #pragma unroll
        for (int j8 = 0; j8 < 8; j8++) {
            __align__(16) __nv_bfloat16 hs[8], ls[8];
            #pragma unroll
            for (int j = 0; j < 8; j++) {
                float v = tileC[(seg * 64 + j8 * 8 + j) * 132 + od];
                __nv_bfloat16 h = __float2bfloat16(v);
                hs[j] = h; ls[j] = __float2bfloat16(v - __bfloat162float(h));
            }
            size_t ob = (size_t)(b * DD + od) * SS + s0 + seg * 64 + j8 * 8;
            *reinterpret_cast<uint4*>(&g_Vth[ob]) = *reinterpret_cast<uint4*>(hs);
            *reinterpret_cast<uint4*>(&g_Vtl[ob]) = *reinterpret_cast<uint4*>(ls);
        }
    }
}

// ---- flash attention v2: 2 CTAs/SM (phase-breaking), BQ=64, BK=32 ----
#define BQ 64
#define BK 32
#define QH_OFF 0
#define QL_OFF 16384
#define K_OFF  32768
#define KSTAGE 16384      /* [Kh 8K | Kl 8K] */
#define V_OFF  65536
#define VSTAGE 16384      /* [Vh 8K | Vl 8K] */
#define RK_OFF 98304
#define FSMEM_TOTAL (RK_OFF + 256)
#define NT (SS / BK)
#define FTH 128

__global__ __launch_bounds__(FTH, 2) void flash_mma_kernel(float* __restrict__ outp) {
    extern __shared__ char smem[];
    const uint32_t sb = smem_u32(smem);
    const int t = threadIdx.x, w = t >> 5, lane = t & 31;
    const int b = blockIdx.x >> 6, qt = blockIdx.x & 63;   // 64 q-tiles of 64 rows per batch
    const int qtok = b * SS + qt * BQ;
    const int m0 = w * 16;
    const int g = lane >> 3, rr = lane & 7;
    const int rowA = m0 + ((g & 1) << 3) + rr;  const int hA = g >> 1;
    const int rowB8 = ((g >> 1) << 3) + rr;      const int hB = g & 1;

    auto issue_stage = [&](int kt) {
        const uint32_t kb = sb + K_OFF + (uint32_t)(kt & 1) * KSTAGE;
        const uint32_t vb = sb + V_OFF + (uint32_t)(kt & 1) * VSTAGE;
        const int ktok = b * SS + kt * BK;
        #pragma unroll
        for (int it = 0; it < 4; it++) {
            int lin = t + it * FTH;                 // 0..511
            int kr = lin >> 4, kc = lin & 15;       // K: 32 rows x 16 chunks
            cpasync16(kb + sw256(kr, kc), g_Kh + (size_t)(ktok + kr) * DD + kc * 8);
            cpasync16(kb + 8192 + sw256(kr, kc), g_Kl + (size_t)(ktok + kr) * DD + kc * 8);
            int vr = lin >> 2, vc = lin & 3;        // V: 128 rows x 4 chunks
            size_t vsrc = (size_t)(b * DD + vr) * SS + kt * BK + vc * 8;
            cpasync16(vb + sw64(vr, vc), g_Vth + vsrc);
            cpasync16(vb + 8192 + sw64(vr, vc), g_Vtl + vsrc);
        }
        if (t < 8) cpasync16(sb + RK_OFF + (kt & 1) * 128 + t * 16, g_rk + ktok + t * 4);
        CP_COMMIT();
    };

    issue_stage(0);

    // Q tiles (plain loads, overlap with cp.async): 64 rows h/l
    #pragma unroll
    for (int it = 0; it < 8; it++) {
        int lin = t + it * FTH;                     // 0..1023
        int r = lin >> 4, c = lin & 15;
        *reinterpret_cast<uint4*>(smem + QH_OFF + sw256(r, c)) =
            *reinterpret_cast<const uint4*>(g_Qh + (size_t)(qtok + r) * DD + c * 8);
        *reinterpret_cast<uint4*>(smem + QL_OFF + sw256(r, c)) =
            *reinterpret_cast<const uint4*>(g_Ql + (size_t)(qtok + r) * DD + c * 8);
    }
    const int r0g = qtok + m0 + (lane >> 2);
    const float rq0 = g_rq[r0g], rq1 = g_rq[r0g + 8];

    float o[16][4];
    #pragma unroll
    for (int i = 0; i < 16; i++) { o[i][0] = o[i][1] = o[i][2] = o[i][3] = 0.f; }
    float mr0 = -INFINITY, mr1 = -INFINITY, lr0 = 0.f, lr1 = 0.f;

    for (int kt = 0; kt < NT; kt++) {
        const uint32_t kb = sb + K_OFF + (uint32_t)(kt & 1) * KSTAGE;
        const uint32_t vb = sb + V_OFF + (uint32_t)(kt & 1) * VSTAGE;
        const float* smk = (const float*)(smem + RK_OFF + (kt & 1) * 128);
        if (kt + 1 < NT) { issue_stage(kt + 1); CP_WAIT1(); }
        else             { CP_WAIT0(); }
        __syncthreads();      // stage kt visible

        // ---- S = Qc·Kc' (3-pass), 16x32 per warp ----
        float S[4][4];
        #pragma unroll
        for (int i = 0; i < 4; i++) { S[i][0] = S[i][1] = S[i][2] = S[i][3] = 0.f; }
        #pragma unroll
        for (int kc = 0; kc < 8; kc++) {
            uint32_t Ah[4], Al[4];
            ldsm4(Ah, sb + QH_OFF + sw256(rowA, kc * 2 + hA));
            ldsm4(Al, sb + QL_OFF + sw256(rowA, kc * 2 + hA));
            #pragma unroll
            for (int np = 0; np < 2; np++) {
                uint32_t Bh[4], Bl[4];
                ldsm4(Bh, kb + sw256(np * 16 + rowB8, kc * 2 + hB));
                ldsm4(Bl, kb + 8192 + sw256(np * 16 + rowB8, kc * 2 + hB));
                mma16816(S[2 * np], Ah, Bh);     mma16816(S[2 * np + 1], Ah, Bh + 2);
                mma16816(S[2 * np], Ah, Bl);     mma16816(S[2 * np + 1], Ah, Bl + 2);
                mma16816(S[2 * np], Al, Bh);     mma16816(S[2 * np + 1], Al, Bh + 2);
            }
        }

        // ---- rank-1 + online softmax (rows warp-local) ----
        const int cbase = 2 * (lane & 3);
        float tm0 = -INFINITY, tm1 = -INFINITY;
        #pragma unroll
        for (int nt = 0; nt < 4; nt++) {
            float2 mk2 = *reinterpret_cast<const float2*>(&smk[nt * 8 + cbase]);
            S[nt][0] += rq0 * mk2.x; S[nt][1] += rq0 * mk2.y;
            S[nt][2] += rq1 * mk2.x; S[nt][3] += rq1 * mk2.y;
            tm0 = fmaxf(tm0, fmaxf(S[nt][0], S[nt][1]));
            tm1 = fmaxf(tm1, fmaxf(S[nt][2], S[nt][3]));
        }
        tm0 = fmaxf(tm0, __shfl_xor_sync(0xFFFFFFFFu, tm0, 1));
        tm0 = fmaxf(tm0, __shfl_xor_sync(0xFFFFFFFFu, tm0, 2));
        tm1 = fmaxf(tm1, __shfl_xor_sync(0xFFFFFFFFu, tm1, 1));
        tm1 = fmaxf(tm1, __shfl_xor_sync(0xFFFFFFFFu, tm1, 2));
        float nm0 = fmaxf(mr0, tm0), nm1 = fmaxf(mr1, tm1);
        float al0 = __expf(mr0 - nm0), al1 = __expf(mr1 - nm1);
        mr0 = nm0; mr1 = nm1;

        uint32_t PhL[4], PhH[4], PlL[4], PlH[4];
        float s0 = 0.f, s1 = 0.f;
        #pragma unroll
        for (int nt = 0; nt < 4; nt++) {
            float p0 = __expf(S[nt][0] - nm0), p1 = __expf(S[nt][1] - nm0);
            float p2 = __expf(S[nt][2] - nm1), p3 = __expf(S[nt][3] - nm1);
            s0 += p0 + p1; s1 += p2 + p3;
            float h0 = __bfloat162float(__float2bfloat16(p0));
            float h1 = __bfloat162float(__float2bfloat16(p1));
            float h2 = __bfloat162float(__float2bfloat16(p2));
            float h3 = __bfloat162float(__float2bfloat16(p3));
            PhL[nt] = pack_bf16x2(h0, h1); PhH[nt] = pack_bf16x2(h2, h3);
            PlL[nt] = pack_bf16x2(p0 - h0, p1 - h1);
            PlH[nt] = pack_bf16x2(p2 - h2, p3 - h3);
        }
        s0 += __shfl_xor_sync(0xFFFFFFFFu, s0, 1);
        s0 += __shfl_xor_sync(0xFFFFFFFFu, s0, 2);
        s1 += __shfl_xor_sync(0xFFFFFFFFu, s1, 1);
        s1 += __shfl_xor_sync(0xFFFFFFFFu, s1, 2);
        lr0 = lr0 * al0 + s0; lr1 = lr1 * al1 + s1;
        if (al0 != 1.f || al1 != 1.f) {
            #pragma unroll
            for (int i = 0; i < 16; i++) { o[i][0] *= al0; o[i][1] *= al0; o[i][2] *= al1; o[i][3] *= al1; }
        }

        // ---- O += P·V (3-pass) ----
        #pragma unroll
        for (int kc = 0; kc < 2; kc++) {
            uint32_t Aph[4] = {PhL[2 * kc], PhH[2 * kc], PhL[2 * kc + 1], PhH[2 * kc + 1]};
            uint32_t Apl[4] = {PlL[2 * kc], PlH[2 * kc], PlL[2 * kc + 1], PlH[2 * kc + 1]};
            #pragma unroll
            for (int dp = 0; dp < 8; dp++) {
                uint32_t Bh[4], Bl[4];
                ldsm4(Bh, vb + sw64(dp * 16 + rowB8, kc * 2 + hB));
                ldsm4(Bl, vb + 8192 + sw64(dp * 16 + rowB8, kc * 2 + hB));
                mma16816(o[2 * dp], Aph, Bh);     mma16816(o[2 * dp + 1], Aph, Bh + 2);
                mma16816(o[2 * dp], Aph, Bl);     mma16816(o[2 * dp + 1], Aph, Bl + 2);
                mma16816(o[2 * dp], Apl, Bh);     mma16816(o[2 * dp + 1], Apl, Bh + 2);
            }
        }
        __syncthreads();      // all reads of stage kt done before it is overwritten
    }

    const float inv0 = 1.f / lr0, inv1 = 1.f / lr1;
    #pragma unroll
    for (int nt = 0; nt < 16; nt++) {
        int col = nt * 8 + 2 * (lane & 3);
        *reinterpret_cast<float2*>(outp + (size_t)r0g * DD + col) =
            make_float2(o[nt][0] * inv0, o[nt][1] * inv0);
        *reinterpret_cast<float2*>(outp + (size_t)(r0g + 8) * DD + col) =
            make_float2(o[nt][2] * inv1, o[nt][3] * inv1);
    }
}

extern "C" void kernel_launch(void* const* d_in, const int* in_sizes, int n_in,
                              void* d_out, int out_size) {
    const float* x  = (const float*)d_in[0];
    const float* wq = (const float*)d_in[2];
    const float* wk = (const float*)d_in[3];
    const float* wv = (const float*)d_in[4];
    float* out = (float*)d_out;

    cudaFuncSetAttribute(proj_kernel, cudaFuncAttributeMaxDynamicSharedMemorySize, PSMEM);
    cudaFuncSetAttribute(flash_mma_kernel, cudaFuncAttributeMaxDynamicSharedMemorySize, FSMEM_TOTAL);

    proj_kernel<<<dim3(128, 3), 256, PSMEM>>>(x, wq, wk, wv);
    flash_mma_kernel<<<BB * (SS / BQ), FTH, FSMEM_TOTAL>>>(out);
}

// round 13
// speedup vs baseline: 1.1799x; 1.1799x over previous
#include <cuda_runtime.h>
#include <cuda_bf16.h>
#include <cuda_fp16.h>
#include <math.h>
#include <stdint.h>

#define DD 128
#define SS 4096
#define BB 4

__device__ __nv_bfloat16 g_Qh[BB * SS * DD];
__device__ __nv_bfloat16 g_Ql[BB * SS * DD];
__device__ __nv_bfloat16 g_Kh[BB * SS * DD];
__device__ __nv_bfloat16 g_Kl[BB * SS * DD];
__device__ __nv_bfloat16 g_Vth[BB * DD * SS];   // [b*128+d][token]
__device__ __nv_bfloat16 g_Vtl[BB * DD * SS];
__device__ float g_rq[BB * SS];
__device__ float g_rk[BB * SS];

// ---- PTX helpers (arch-portable) ----
__device__ __forceinline__ uint32_t smem_u32(const void* p) {
    uint32_t a;
    asm("{ .reg .u64 t; cvta.to.shared.u64 t, %1; cvt.u32.u64 %0, t; }" : "=r"(a) : "l"(p));
    return a;
}
__device__ __forceinline__ void ldsm4(uint32_t* d, uint32_t addr) {
    asm volatile("ldmatrix.sync.aligned.m8n8.x4.shared.b16 {%0,%1,%2,%3}, [%4];"
                 : "=r"(d[0]), "=r"(d[1]), "=r"(d[2]), "=r"(d[3]) : "r"(addr));
}
__device__ __forceinline__ void mma16816(float* c, const uint32_t* a, const uint32_t* b) {
    asm volatile("mma.sync.aligned.m16n8k16.row.col.f32.bf16.bf16.f32 "
                 "{%0,%1,%2,%3}, {%4,%5,%6,%7}, {%8,%9}, {%0,%1,%2,%3};"
                 : "+f"(c[0]), "+f"(c[1]), "+f"(c[2]), "+f"(c[3])
                 : "r"(a[0]), "r"(a[1]), "r"(a[2]), "r"(a[3]), "r"(b[0]), "r"(b[1]));
}
__device__ __forceinline__ void mma16816h(float* c, const uint32_t* a, const uint32_t* b) {
    asm volatile("mma.sync.aligned.m16n8k16.row.col.f32.f16.f16.f32 "
                 "{%0,%1,%2,%3}, {%4,%5,%6,%7}, {%8,%9}, {%0,%1,%2,%3};"
                 : "+f"(c[0]), "+f"(c[1]), "+f"(c[2]), "+f"(c[3])
                 : "r"(a[0]), "r"(a[1]), "r"(a[2]), "r"(a[3]), "r"(b[0]), "r"(b[1]));
}
__device__ __forceinline__ uint32_t pack_bf16x2(float lo, float hi) {
    uint32_t r;
    asm("cvt.rn.bf16x2.f32 %0, %1, %2;" : "=r"(r) : "f"(hi), "f"(lo));
    return r;
}
__device__ __forceinline__ void cpasync16(uint32_t s, const void* g) {
    asm volatile("cp.async.cg.shared.global [%0], [%1], 16;" :: "r"(s), "l"(g));
}
#define MBAR_INIT(a, c) asm volatile("mbarrier.init.shared.b64 [%0], %1;" :: "r"((uint32_t)(a)), "r"((uint32_t)(c)) : "memory")
#define MBAR_ARRIVE(a)  asm volatile("mbarrier.arrive.shared.b64 _, [%0];" :: "r"((uint32_t)(a)) : "memory")
// NOTE: .noinc — completion-arrive counts against the expected 256 arrivals.
// The default form increments pending count at issue (net zero) => deadlock (R11 bug).
#define CPA_MBAR_ARRIVE(a) asm volatile("cp.async.mbarrier.arrive.noinc.shared.b64 [%0];" :: "r"((uint32_t)(a)) : "memory")
#define MBAR_WAIT(a, par) do { uint32_t _m=(uint32_t)(a), _p=(uint32_t)(par), _d; \
    asm volatile("{\n\t.reg .pred p;\n\tmbarrier.try_wait.parity.acquire.cta.shared::cta.b64 p,[%1],%2;\n\tselp.b32 %0,1,0,p;\n\t}" : "=r"(_d) : "r"(_m), "r"(_p) : "memory"); \
    if (!_d) asm volatile("{\n\t.reg .pred P1;\n\tWL_%=:\n\tmbarrier.try_wait.parity.acquire.cta.shared::cta.b64 P1,[%0],%1,0x989680;\n\t@P1 bra.uni WD_%=;\n\tbra.uni WL_%=;\n\tWD_%=:\n\t}" :: "r"(_m), "r"(_p) : "memory"); } while (0)

__device__ __forceinline__ uint32_t sw256(int r, int c16) {   // 256B rows
    return (uint32_t)(r * 256 + (((c16 & 8) | ((c16 & 7) ^ (r & 7))) << 4));
}
__device__ __forceinline__ uint32_t sw128(int r, int c8) {    // 128B rows
    return (uint32_t)(r * 128 + (((c8 ^ r) & 7) << 4));
}

// ================= fused QKV projection + center/split/transpose =============
#define PA_H 0
#define PA_L 32768
#define PB_H 65536
#define PB_L 98304
#define PC_OFF 131072
#define PR_OFF (PC_OFF + 128 * 132 * 4)
#define PSMEM  (PR_OFF + 1024)

__global__ __launch_bounds__(256, 1) void proj_kernel(const float* __restrict__ xg,
                                                      const float* __restrict__ wq,
                                                      const float* __restrict__ wk,
                                                      const float* __restrict__ wv) {
    extern __shared__ char smem[];
    const uint32_t sb = smem_u32(smem);
    float* tileC = (float*)(smem + PC_OFF);
    float* rmean = (float*)(smem + PR_OFF);
    const int t = threadIdx.x, w = t >> 5, lane = t & 31;
    const int tile = blockIdx.x, proj = blockIdx.y;
    const int tok0 = tile * 128;
    const int b = tok0 >> 12, s0 = tok0 & (SS - 1);
    const float* W = (proj == 0) ? wq : (proj == 1) ? wk : wv;
    const float SCALE = 0.08838834764831845f;

    #pragma unroll
    for (int it = 0; it < 8; it++) {
        int lin = t + it * 256;
        int r = lin >> 4, c16 = lin & 15;
        const float* src = xg + (size_t)(tok0 + r) * DD + c16 * 8;
        float4 v0 = *reinterpret_cast<const float4*>(src);
        float4 v1 = *reinterpret_cast<const float4*>(src + 4);
        __half2 h0 = __floats2half2_rn(v0.x, v0.y), h1 = __floats2half2_rn(v0.z, v0.w);
        __half2 h2 = __floats2half2_rn(v1.x, v1.y), h3 = __floats2half2_rn(v1.z, v1.w);
        float2 f0 = __half22float2(h0), f1 = __half22float2(h1);
        float2 f2 = __half22float2(h2), f3 = __half22float2(h3);
        __half2 l0 = __floats2half2_rn(v0.x - f0.x, v0.y - f0.y);
        __half2 l1 = __floats2half2_rn(v0.z - f1.x, v0.w - f1.y);
        __half2 l2 = __floats2half2_rn(v1.x - f2.x, v1.y - f2.y);
        __half2 l3 = __floats2half2_rn(v1.z - f3.x, v1.w - f3.y);
        uint4 hv = make_uint4(*(uint32_t*)&h0, *(uint32_t*)&h1, *(uint32_t*)&h2, *(uint32_t*)&h3);
        uint4 lv = make_uint4(*(uint32_t*)&l0, *(uint32_t*)&l1, *(uint32_t*)&l2, *(uint32_t*)&l3);
        *reinterpret_cast<uint4*>(smem + PA_H + sw256(r, c16)) = hv;
        *reinterpret_cast<uint4*>(smem + PA_L + sw256(r, c16)) = lv;
    }
    #pragma unroll
    for (int it = 0; it < 8; it++) {
        int lin = t + it * 256;
        int d = lin >> 4, c16 = lin & 15;
        const float* src = W + (size_t)d * DD + c16 * 8;
        float wv[8];
        *reinterpret_cast<float4*>(wv) = *reinterpret_cast<const float4*>(src);
        *reinterpret_cast<float4*>(wv + 4) = *reinterpret_cast<const float4*>(src + 4);
        #pragma unroll
        for (int j = 0; j < 8; j++) {
            int e = c16 * 8 + j;
            __half h = __float2half_rn(wv[j]);
            __half l = __float2half_rn(wv[j] - __half2float(h));
            uint32_t off = sw256(e, d >> 3) + (d & 7) * 2;
            *reinterpret_cast<__half*>(smem + PB_H + off) = h;
            *reinterpret_cast<__half*>(smem + PB_L + off) = l;
        }
    }
    __syncthreads();

    const int m0 = w * 16;
    const int g = lane >> 3, rr = lane & 7;
    const int rowA = m0 + ((g & 1) << 3) + rr;  const int hA = g >> 1;
    const int rowB8 = ((g >> 1) << 3) + rr;      const int hB = g & 1;

    float C[16][4];
    #pragma unroll
    for (int i = 0; i < 16; i++) { C[i][0] = C[i][1] = C[i][2] = C[i][3] = 0.f; }
    #pragma unroll
    for (int kc = 0; kc < 8; kc++) {
        uint32_t Ah[4], Al[4];
        ldsm4(Ah, sb + PA_H + sw256(rowA, kc * 2 + hA));
        ldsm4(Al, sb + PA_L + sw256(rowA, kc * 2 + hA));
        #pragma unroll
        for (int np = 0; np < 8; np++) {
            uint32_t Bh[4], Bl[4];
            ldsm4(Bh, sb + PB_H + sw256(np * 16 + rowB8, kc * 2 + hB));
            ldsm4(Bl, sb + PB_L + sw256(np * 16 + rowB8, kc * 2 + hB));
            mma16816h(C[2 * np], Ah, Bh);     mma16816h(C[2 * np + 1], Ah, Bh + 2);
            mma16816h(C[2 * np], Ah, Bl);     mma16816h(C[2 * np + 1], Ah, Bl + 2);
            mma16816h(C[2 * np], Al, Bh);     mma16816h(C[2 * np + 1], Al, Bh + 2);
        }
    }
    __syncthreads();

    const int lr = lane >> 2, lc = 2 * (lane & 3);
    #pragma unroll
    for (int np = 0; np < 8; np++) {
        #pragma unroll
        for (int nn = 0; nn < 2; nn++) {
            int c0 = np * 16 + nn * 8 + lc;
            float* p0 = tileC + (m0 + lr) * 132 + c0;
            float* p1 = tileC + (m0 + lr + 8) * 132 + c0;
            p0[0] = C[np * 2 + nn][0]; p0[1] = C[np * 2 + nn][1];
            p1[0] = C[np * 2 + nn][2]; p1[1] = C[np * 2 + nn][3];
        }
    }
    __syncthreads();

    if (proj < 2) {
        const int r = t >> 1, part = t & 1;
        float s = 0.f;
        #pragma unroll
        for (int j = 0; j < 16; j++) {
            float4 v = *reinterpret_cast<float4*>(tileC + r * 132 + part * 64 + j * 4);
            s += v.x + v.y + v.z + v.w;
        }
        s += __shfl_xor_sync(0xFFFFFFFFu, s, 1);
        if (proj == 0) {
            float rq = s * SCALE;
            if (part == 0) { rmean[r] = rq * (1.f / 128.f); g_rq[tok0 + r] = rq; }
        } else {
            float mk = s * (1.f / 128.f);
            if (part == 0) { rmean[r] = mk; g_rk[tok0 + r] = mk; }
        }
        __syncthreads();
        const float mu = rmean[r];
        __nv_bfloat16* gh = (proj == 0) ? g_Qh : g_Kh;
        __nv_bfloat16* gl = (proj == 0) ? g_Ql : g_Kl;
        const float fac = (proj == 0) ? SCALE : 1.f;
        #pragma unroll
        for (int j8 = 0; j8 < 8; j8++) {
            int c = part * 64 + j8 * 8;
            __align__(16) __nv_bfloat16 hs[8], ls[8];
            #pragma unroll
            for (int j = 0; j < 8; j++) {
                float v = tileC[r * 132 + c + j] * fac - mu;
                __nv_bfloat16 h = __float2bfloat16(v);
                hs[j] = h; ls[j] = __float2bfloat16(v - __bfloat162float(h));
            }
            size_t ob = (size_t)(tok0 + r) * DD + c;
            *reinterpret_cast<uint4*>(&gh[ob]) = *reinterpret_cast<uint4*>(hs);
            *reinterpret_cast<uint4*>(&gl[ob]) = *reinterpret_cast<uint4*>(ls);
        }
    } else {
        const int od = t >> 1, seg = t & 1;
        #pragma unroll
        for (int j8 = 0; j8 < 8; j8++) {
            __align__(16) __nv_bfloat16 hs[8], ls[8];
            #pragma unroll
            for (int j = 0; j < 8; j++) {
                float v = tileC[(seg * 64 + j8 * 8 + j) * 132 + od];
                __nv_bfloat16 h = __float2bfloat16(v);
                hs[j] = h; ls[j] = __float2bfloat16(v - __bfloat162float(h));
            }
            size_t ob = (size_t)(b * DD + od) * SS + s0 + seg * 64 + j8 * 8;
            *reinterpret_cast<uint4*>(&g_Vth[ob]) = *reinterpret_cast<uint4*>(hs);
            *reinterpret_cast<uint4*>(&g_Vtl[ob]) = *reinterpret_cast<uint4*>(ls);
        }
    }
}

// ---- flash attention v3: mbarrier pipeline, K ring x2, V+rk ring x3 ----
#define BQ 128
#define BK 64
#define QH_OFF 0
#define QL_OFF 32768
#define K_OFF  65536
#define KSTAGE 32768      /* [Kh 16K | Kl 16K] */
#define V_OFF  131072
#define VSTAGE 32768      /* [Vh 16K | Vl 16K] x3 */
#define RK3_OFF 229376    /* 3 x 256 B */
#define MB_OFF  230144    /* fK0 fK1 eK0 eK1 fV0 fV1 fV2 eV0 eV1 eV2 */
#define FSMEM_TOTAL 230272
#define NT (SS / BK)

__global__ __launch_bounds__(256, 1) void flash_mma_kernel(float* __restrict__ outp) {
    extern __shared__ char smem[];
    const uint32_t sb = smem_u32(smem);
    const uint32_t mb = sb + MB_OFF;
    const int t = threadIdx.x, w = t >> 5, lane = t & 31;
    const int b = blockIdx.x >> 5, qt = blockIdx.x & 31;
    const int qtok = b * SS + qt * BQ;
    const int m0 = w * 16;
    const int g = lane >> 3, rr = lane & 7;
    const int rowA = m0 + ((g & 1) << 3) + rr;  const int hA = g >> 1;
    const int rowB8 = ((g >> 1) << 3) + rr;      const int hB = g & 1;

    if (t == 0) {
        #pragma unroll
        for (int i = 0; i < 10; i++) MBAR_INIT(mb + i * 8, 256);
    }

    // producer: tile p.  waits gate buffer reuse; arrivals signal data-ready.
    auto produce = [&](int p) {
        const int s2 = p & 1;
        const int s3 = p - (p / 3) * 3;
        if (p >= 2) MBAR_WAIT(mb + 16 + s2 * 8, ((p >> 1) - 1) & 1);             // empty_K: qk(p-2) readers
        if (p >= 3) MBAR_WAIT(mb + 56 + s3 * 8, ((p - s3) / 3 - 1) & 1);         // empty_V: pv(p-3) readers
        const int ktok = b * SS + p * BK;
        const uint32_t kb = sb + K_OFF + (uint32_t)s2 * KSTAGE;
        if (t < 16) cpasync16(sb + RK3_OFF + s3 * 256 + t * 16, g_rk + ktok + t * 4);
        #pragma unroll
        for (int it = 0; it < 4; it++) {
            int lin = t + it * 256;
            int kr = lin >> 4, kc = lin & 15;
            cpasync16(kb + sw256(kr, kc), g_Kh + (size_t)(ktok + kr) * DD + kc * 8);
            cpasync16(kb + 16384 + sw256(kr, kc), g_Kl + (size_t)(ktok + kr) * DD + kc * 8);
        }
        CPA_MBAR_ARRIVE(mb + s2 * 8);                                            // full_K (also covers rk)
        const uint32_t vb = sb + V_OFF + (uint32_t)s3 * VSTAGE;
        #pragma unroll
        for (int it = 0; it < 4; it++) {
            int lin = t + it * 256;
            int vr = lin >> 3, vc = lin & 7;
            size_t vsrc = (size_t)(b * DD + vr) * SS + p * BK + vc * 8;
            cpasync16(vb + sw128(vr, vc), g_Vth + vsrc);
            cpasync16(vb + 16384 + sw128(vr, vc), g_Vtl + vsrc);
        }
        CPA_MBAR_ARRIVE(mb + 32 + s3 * 8);                                       // full_V
    };

    produce(0);
    produce(1);

    // Q tiles (plain loads, overlap with cp.async)
    #pragma unroll
    for (int it = 0; it < 8; it++) {
        int lin = t + it * 256, r = lin >> 4, c = lin & 15;
        *reinterpret_cast<uint4*>(smem + QH_OFF + sw256(r, c)) =
            *reinterpret_cast<const uint4*>(g_Qh + (size_t)(qtok + r) * DD + c * 8);
        *reinterpret_cast<uint4*>(smem + QL_OFF + sw256(r, c)) =
            *reinterpret_cast<const uint4*>(g_Ql + (size_t)(qtok + r) * DD + c * 8);
    }
    const int r0g = qtok + m0 + (lane >> 2);
    const float rq0 = g_rq[r0g], rq1 = g_rq[r0g + 8];

    float o[16][4];
    #pragma unroll
    for (int i = 0; i < 16; i++) { o[i][0] = o[i][1] = o[i][2] = o[i][3] = 0.f; }
    float mr0 = -INFINITY, mr1 = -INFINITY, lr0 = 0.f, lr1 = 0.f;

    __syncthreads();   // Q visible + mbarriers initialized (one-time)

    for (int kt = 0; kt < NT; kt++) {
        const int s2 = kt & 1;
        const int s3 = kt - (kt / 3) * 3;
        const uint32_t kb = sb + K_OFF + (uint32_t)s2 * KSTAGE;
        const uint32_t vb = sb + V_OFF + (uint32_t)s3 * VSTAGE;
        const float* smk = (const float*)(smem + RK3_OFF + s3 * 256);

        MBAR_WAIT(mb + s2 * 8, (kt >> 1) & 1);          // full_K (data + rk ready)

        // ---- S = Qc·Kc' (3-pass), 16x64 per warp ----
        float S[8][4];
        #pragma unroll
        for (int i = 0; i < 8; i++) { S[i][0] = S[i][1] = S[i][2] = S[i][3] = 0.f; }
        #pragma unroll
        for (int kc = 0; kc < 8; kc++) {
            uint32_t Ah[4], Al[4];
            ldsm4(Ah, sb + QH_OFF + sw256(rowA, kc * 2 + hA));
            ldsm4(Al, sb + QL_OFF + sw256(rowA, kc * 2 + hA));
            #pragma unroll
            for (int np = 0; np < 4; np++) {
                uint32_t Bh[4], Bl[4];
                ldsm4(Bh, kb + sw256(np * 16 + rowB8, kc * 2 + hB));
                ldsm4(Bl, kb + 16384 + sw256(np * 16 + rowB8, kc * 2 + hB));
                mma16816(S[2 * np], Ah, Bh);     mma16816(S[2 * np + 1], Ah, Bh + 2);
                mma16816(S[2 * np], Ah, Bl);     mma16816(S[2 * np + 1], Ah, Bl + 2);
                mma16816(S[2 * np], Al, Bh);     mma16816(S[2 * np + 1], Al, Bh + 2);
            }
        }
        MBAR_ARRIVE(mb + 16 + s2 * 8);                  // empty_K: K reads done (early)

        // ---- rank-1 + online softmax ----
        const int cbase = 2 * (lane & 3);
        float tm0 = -INFINITY, tm1 = -INFINITY;
        #pragma unroll
        for (int nt = 0; nt < 8; nt++) {
            float2 mk2 = *reinterpret_cast<const float2*>(&smk[nt * 8 + cbase]);
            S[nt][0] += rq0 * mk2.x; S[nt][1] += rq0 * mk2.y;
            S[nt][2] += rq1 * mk2.x; S[nt][3] += rq1 * mk2.y;
            tm0 = fmaxf(tm0, fmaxf(S[nt][0], S[nt][1]));
            tm1 = fmaxf(tm1, fmaxf(S[nt][2], S[nt][3]));
        }
        tm0 = fmaxf(tm0, __shfl_xor_sync(0xFFFFFFFFu, tm0, 1));
        tm0 = fmaxf(tm0, __shfl_xor_sync(0xFFFFFFFFu, tm0, 2));
        tm1 = fmaxf(tm1, __shfl_xor_sync(0xFFFFFFFFu, tm1, 1));
        tm1 = fmaxf(tm1, __shfl_xor_sync(0xFFFFFFFFu, tm1, 2));
        float nm0 = fmaxf(mr0, tm0), nm1 = fmaxf(mr1, tm1);
        float al0 = __expf(mr0 - nm0), al1 = __expf(mr1 - nm1);
        mr0 = nm0; mr1 = nm1;

        uint32_t PhL[8], PhH[8], PlL[8], PlH[8];
        float s0 = 0.f, s1 = 0.f;
        #pragma unroll
        for (int nt = 0; nt < 8; nt++) {
            float p0 = __expf(S[nt][0] - nm0), p1 = __expf(S[nt][1] - nm0);
            float p2 = __expf(S[nt][2] - nm1), p3 = __expf(S[nt][3] - nm1);
            s0 += p0 + p1; s1 += p2 + p3;
            float h0 = __bfloat162float(__float2bfloat16(p0));
            float h1 = __bfloat162float(__float2bfloat16(p1));
            float h2 = __bfloat162float(__float2bfloat16(p2));
            float h3 = __bfloat162float(__float2bfloat16(p3));
            PhL[nt] = pack_bf16x2(h0, h1); PhH[nt] = pack_bf16x2(h2, h3);
            PlL[nt] = pack_bf16x2(p0 - h0, p1 - h1);
            PlH[nt] = pack_bf16x2(p2 - h2, p3 - h3);
        }
        s0 += __shfl_xor_sync(0xFFFFFFFFu, s0, 1);
        s0 += __shfl_xor_sync(0xFFFFFFFFu, s0, 2);
        s1 += __shfl_xor_sync(0xFFFFFFFFu, s1, 1);
        s1 += __shfl_xor_sync(0xFFFFFFFFu, s1, 2);
        lr0 = lr0 * al0 + s0; lr1 = lr1 * al1 + s1;
        #pragma unroll
        for (int i = 0; i < 16; i++) { o[i][0] *= al0; o[i][1] *= al0; o[i][2] *= al1; o[i][3] *= al1; }

        MBAR_WAIT(mb + 32 + s3 * 8, (kt / 3) & 1);      // full_V (latest possible)

        // ---- O += P·V (3-pass) ----
        #pragma unroll
        for (int kc = 0; kc < 4; kc++) {
            uint32_t Aph[4] = {PhL[2 * kc], PhH[2 * kc], PhL[2 * kc + 1], PhH[2 * kc + 1]};
            uint32_t Apl[4] = {PlL[2 * kc], PlH[2 * kc], PlL[2 * kc + 1], PlH[2 * kc + 1]};
            #pragma unroll
            for (int dp = 0; dp < 8; dp++) {
                uint32_t Bh[4], Bl[4];
                ldsm4(Bh, vb + sw128(dp * 16 + rowB8, kc * 2 + hB));
                ldsm4(Bl, vb + 16384 + sw128(dp * 16 + rowB8, kc * 2 + hB));
                mma16816(o[2 * dp], Aph, Bh);     mma16816(o[2 * dp + 1], Aph, Bh + 2);
                mma16816(o[2 * dp], Aph, Bl);     mma16816(o[2 * dp + 1], Aph, Bl + 2);
                mma16816(o[2 * dp], Apl, Bh);     mma16816(o[2 * dp + 1], Apl, Bh + 2);
            }
        }
        MBAR_ARRIVE(mb + 56 + s3 * 8);                  // empty_V (+rk) reads done

        if (kt + 2 < NT) produce(kt + 2);
    }

    const float inv0 = 1.f / lr0, inv1 = 1.f / lr1;
    #pragma unroll
    for (int nt = 0; nt < 16; nt++) {
        int col = nt * 8 + 2 * (lane & 3);
        *reinterpret_cast<float2*>(outp + (size_t)r0g * DD + col) =
            make_float2(o[nt][0] * inv0, o[nt][1] * inv0);
        *reinterpret_cast<float2*>(outp + (size_t)(r0g + 8) * DD + col) =
            make_float2(o[nt][2] * inv1, o[nt][3] * inv1);
    }
}

extern "C" void kernel_launch(void* const* d_in, const int* in_sizes, int n_in,
                              void* d_out, int out_size) {
    const float* x  = (const float*)d_in[0];
    const float* wq = (const float*)d_in[2];
    const float* wk = (const float*)d_in[3];
    const float* wv = (const float*)d_in[4];
    float* out = (float*)d_out;

    cudaFuncSetAttribute(proj_kernel, cudaFuncAttributeMaxDynamicSharedMemorySize, PSMEM);
    cudaFuncSetAttribute(flash_mma_kernel, cudaFuncAttributeMaxDynamicSharedMemorySize, FSMEM_TOTAL);

    proj_kernel<<<dim3(128, 3), 256, PSMEM>>>(x, wq, wk, wv);
    flash_mma_kernel<<<BB * (SS / BQ), 256, FSMEM_TOTAL>>>(out);
}

// round 14
// speedup vs baseline: 1.5523x; 1.3157x over previous
#include <cuda_runtime.h>
#include <cuda_bf16.h>
#include <cuda_fp16.h>
#include <math.h>
#include <stdint.h>

#define DD 128
#define SS 4096
#define BB 4

__device__ __half g_Qh[BB * SS * DD];
__device__ __half g_Ql[BB * SS * DD];
__device__ __half g_Kh[BB * SS * DD];
__device__ __half g_Kl[BB * SS * DD];
__device__ __half g_Vth[BB * DD * SS];   // [b*128+d][token], fp16, unsplit
__device__ float g_rq[BB * SS];
__device__ float g_rk[BB * SS];

// ---- PTX helpers (arch-portable) ----
__device__ __forceinline__ uint32_t smem_u32(const void* p) {
    uint32_t a;
    asm("{ .reg .u64 t; cvta.to.shared.u64 t, %1; cvt.u32.u64 %0, t; }" : "=r"(a) : "l"(p));
    return a;
}
__device__ __forceinline__ void ldsm4(uint32_t* d, uint32_t addr) {
    asm volatile("ldmatrix.sync.aligned.m8n8.x4.shared.b16 {%0,%1,%2,%3}, [%4];"
                 : "=r"(d[0]), "=r"(d[1]), "=r"(d[2]), "=r"(d[3]) : "r"(addr));
}
__device__ __forceinline__ void mma16816h(float* c, const uint32_t* a, const uint32_t* b) {
    asm volatile("mma.sync.aligned.m16n8k16.row.col.f32.f16.f16.f32 "
                 "{%0,%1,%2,%3}, {%4,%5,%6,%7}, {%8,%9}, {%0,%1,%2,%3};"
                 : "+f"(c[0]), "+f"(c[1]), "+f"(c[2]), "+f"(c[3])
                 : "r"(a[0]), "r"(a[1]), "r"(a[2]), "r"(a[3]), "r"(b[0]), "r"(b[1]));
}
__device__ __forceinline__ uint32_t pack_half2(float lo, float hi) {
    uint32_t r;
    asm("cvt.rn.f16x2.f32 %0, %1, %2;" : "=r"(r) : "f"(hi), "f"(lo));
    return r;
}
__device__ __forceinline__ void cpasync16(uint32_t s, const void* g) {
    asm volatile("cp.async.cg.shared.global [%0], [%1], 16;" :: "r"(s), "l"(g));
}
#define MBAR_INIT(a, c) asm volatile("mbarrier.init.shared.b64 [%0], %1;" :: "r"((uint32_t)(a)), "r"((uint32_t)(c)) : "memory")
#define MBAR_ARRIVE(a)  asm volatile("mbarrier.arrive.shared.b64 _, [%0];" :: "r"((uint32_t)(a)) : "memory")
#define CPA_MBAR_ARRIVE(a) asm volatile("cp.async.mbarrier.arrive.noinc.shared.b64 [%0];" :: "r"((uint32_t)(a)) : "memory")
#define MBAR_WAIT(a, par) do { uint32_t _m=(uint32_t)(a), _p=(uint32_t)(par), _d; \
    asm volatile("{\n\t.reg .pred p;\n\tmbarrier.try_wait.parity.acquire.cta.shared::cta.b64 p,[%1],%2;\n\tselp.b32 %0,1,0,p;\n\t}" : "=r"(_d) : "r"(_m), "r"(_p) : "memory"); \
    if (!_d) asm volatile("{\n\t.reg .pred P1;\n\tWL_%=:\n\tmbarrier.try_wait.parity.acquire.cta.shared::cta.b64 P1,[%0],%1,0x989680;\n\t@P1 bra.uni WD_%=;\n\tbra.uni WL_%=;\n\tWD_%=:\n\t}" :: "r"(_m), "r"(_p) : "memory"); } while (0)

__device__ __forceinline__ uint32_t sw256(int r, int c16) {   // 256B rows
    return (uint32_t)(r * 256 + (((c16 & 8) | ((c16 & 7) ^ (r & 7))) << 4));
}
__device__ __forceinline__ uint32_t sw128(int r, int c8) {    // 128B rows
    return (uint32_t)(r * 128 + (((c8 ^ r) & 7) << 4));
}

// ================= fused QKV projection + center/split/transpose =============
#define PA_H 0
#define PA_L 32768
#define PB_H 65536
#define PB_L 98304
#define PC_OFF 131072
#define PR_OFF (PC_OFF + 128 * 132 * 4)
#define PSMEM  (PR_OFF + 1024)

__global__ __launch_bounds__(256, 1) void proj_kernel(const float* __restrict__ xg,
                                                      const float* __restrict__ wq,
                                                      const float* __restrict__ wk,
                                                      const float* __restrict__ wv) {
    extern __shared__ char smem[];
    const uint32_t sb = smem_u32(smem);
    float* tileC = (float*)(smem + PC_OFF);
    float* rmean = (float*)(smem + PR_OFF);
    const int t = threadIdx.x, w = t >> 5, lane = t & 31;
    const int tile = blockIdx.x, proj = blockIdx.y;
    const int tok0 = tile * 128;
    const int b = tok0 >> 12, s0 = tok0 & (SS - 1);
    const float* W = (proj == 0) ? wq : (proj == 1) ? wk : wv;
    const float SCALE = 0.08838834764831845f;

    #pragma unroll
    for (int it = 0; it < 8; it++) {
        int lin = t + it * 256;
        int r = lin >> 4, c16 = lin & 15;
        const float* src = xg + (size_t)(tok0 + r) * DD + c16 * 8;
        float4 v0 = *reinterpret_cast<const float4*>(src);
        float4 v1 = *reinterpret_cast<const float4*>(src + 4);
        __half2 h0 = __floats2half2_rn(v0.x, v0.y), h1 = __floats2half2_rn(v0.z, v0.w);
        __half2 h2 = __floats2half2_rn(v1.x, v1.y), h3 = __floats2half2_rn(v1.z, v1.w);
        float2 f0 = __half22float2(h0), f1 = __half22float2(h1);
        float2 f2 = __half22float2(h2), f3 = __half22float2(h3);
        __half2 l0 = __floats2half2_rn(v0.x - f0.x, v0.y - f0.y);
        __half2 l1 = __floats2half2_rn(v0.z - f1.x, v0.w - f1.y);
        __half2 l2 = __floats2half2_rn(v1.x - f2.x, v1.y - f2.y);
        __half2 l3 = __floats2half2_rn(v1.z - f3.x, v1.w - f3.y);
        uint4 hv = make_uint4(*(uint32_t*)&h0, *(uint32_t*)&h1, *(uint32_t*)&h2, *(uint32_t*)&h3);
        uint4 lv = make_uint4(*(uint32_t*)&l0, *(uint32_t*)&l1, *(uint32_t*)&l2, *(uint32_t*)&l3);
        *reinterpret_cast<uint4*>(smem + PA_H + sw256(r, c16)) = hv;
        *reinterpret_cast<uint4*>(smem + PA_L + sw256(r, c16)) = lv;
    }
    #pragma unroll
    for (int it = 0; it < 8; it++) {
        int lin = t + it * 256;
        int d = lin >> 4, c16 = lin & 15;
        const float* src = W + (size_t)d * DD + c16 * 8;
        float wv[8];
        *reinterpret_cast<float4*>(wv) = *reinterpret_cast<const float4*>(src);
        *reinterpret_cast<float4*>(wv + 4) = *reinterpret_cast<const float4*>(src + 4);
        #pragma unroll
        for (int j = 0; j < 8; j++) {
            int e = c16 * 8 + j;
            __half h = __float2half_rn(wv[j]);
            __half l = __float2half_rn(wv[j] - __half2float(h));
            uint32_t off = sw256(e, d >> 3) + (d & 7) * 2;
            *reinterpret_cast<__half*>(smem + PB_H + off) = h;
            *reinterpret_cast<__half*>(smem + PB_L + off) = l;
        }
    }
    __syncthreads();

    const int m0 = w * 16;
    const int g = lane >> 3, rr = lane & 7;
    const int rowA = m0 + ((g & 1) << 3) + rr;  const int hA = g >> 1;
    const int rowB8 = ((g >> 1) << 3) + rr;      const int hB = g & 1;

    float C[16][4];
    #pragma unroll
    for (int i = 0; i < 16; i++) { C[i][0] = C[i][1] = C[i][2] = C[i][3] = 0.f; }
    #pragma unroll
    for (int kc = 0; kc < 8; kc++) {
        uint32_t Ah[4], Al[4];
        ldsm4(Ah, sb + PA_H + sw256(rowA, kc * 2 + hA));
        ldsm4(Al, sb + PA_L + sw256(rowA, kc * 2 + hA));
        #pragma unroll
        for (int np = 0; np < 8; np++) {
            uint32_t Bh[4], Bl[4];
            ldsm4(Bh, sb + PB_H + sw256(np * 16 + rowB8, kc * 2 + hB));
            ldsm4(Bl, sb + PB_L + sw256(np * 16 + rowB8, kc * 2 + hB));
            mma16816h(C[2 * np], Ah, Bh);     mma16816h(C[2 * np + 1], Ah, Bh + 2);
            mma16816h(C[2 * np], Ah, Bl);     mma16816h(C[2 * np + 1], Ah, Bl + 2);
            mma16816h(C[2 * np], Al, Bh);     mma16816h(C[2 * np + 1], Al, Bh + 2);
        }
    }
    __syncthreads();

    const int lr = lane >> 2, lc = 2 * (lane & 3);
    #pragma unroll
    for (int np = 0; np < 8; np++) {
        #pragma unroll
        for (int nn = 0; nn < 2; nn++) {
            int c0 = np * 16 + nn * 8 + lc;
            float* p0 = tileC + (m0 + lr) * 132 + c0;
            float* p1 = tileC + (m0 + lr + 8) * 132 + c0;
            p0[0] = C[np * 2 + nn][0]; p0[1] = C[np * 2 + nn][1];
            p1[0] = C[np * 2 + nn][2]; p1[1] = C[np * 2 + nn][3];
        }
    }
    __syncthreads();

    if (proj < 2) {
        const int r = t >> 1, part = t & 1;
        float s = 0.f;
        #pragma unroll
        for (int j = 0; j < 16; j++) {
            float4 v = *reinterpret_cast<float4*>(tileC + r * 132 + part * 64 + j * 4);
            s += v.x + v.y + v.z + v.w;
        }
        s += __shfl_xor_sync(0xFFFFFFFFu, s, 1);
        if (proj == 0) {
            float rq = s * SCALE;
            if (part == 0) { rmean[r] = rq * (1.f / 128.f); g_rq[tok0 + r] = rq; }
        } else {
            float mk = s * (1.f / 128.f);
            if (part == 0) { rmean[r] = mk; g_rk[tok0 + r] = mk; }
        }
        __syncthreads();
        const float mu = rmean[r];
        __half* gh = (proj == 0) ? g_Qh : g_Kh;
        __half* gl = (proj == 0) ? g_Ql : g_Kl;
        const float fac = (proj == 0) ? SCALE : 1.f;
        #pragma unroll
        for (int j8 = 0; j8 < 8; j8++) {
            int c = part * 64 + j8 * 8;
            __align__(16) __half hs[8], ls[8];
            #pragma unroll
            for (int j = 0; j < 8; j++) {
                float v = tileC[r * 132 + c + j] * fac - mu;
                __half h = __float2half_rn(v);
                hs[j] = h; ls[j] = __float2half_rn(v - __half2float(h));
            }
            size_t ob = (size_t)(tok0 + r) * DD + c;
            *reinterpret_cast<uint4*>(&gh[ob]) = *reinterpret_cast<uint4*>(hs);
            *reinterpret_cast<uint4*>(&gl[ob]) = *reinterpret_cast<uint4*>(ls);
        }
    } else {
        const int od = t >> 1, seg = t & 1;
        #pragma unroll
        for (int j8 = 0; j8 < 8; j8++) {
            __align__(16) __half hs[8];
            #pragma unroll
            for (int j = 0; j < 8; j++)
                hs[j] = __float2half_rn(tileC[(seg * 64 + j8 * 8 + j) * 132 + od]);
            size_t ob = (size_t)(b * DD + od) * SS + s0 + seg * 64 + j8 * 8;
            *reinterpret_cast<uint4*>(&g_Vth[ob]) = *reinterpret_cast<uint4*>(hs);
        }
    }
}

// ---- flash v4: fp16 ops; QK 3-pass, PV 1-pass; mbarrier pipeline ----
#define BQ 128
#define BK 64
#define QH_OFF 0
#define QL_OFF 32768
#define K_OFF  65536
#define KSTAGE 32768      /* [Kh 16K | Kl 16K] x2 */
#define V_OFF  131072
#define VSTAGE 16384      /* [Vh 16K] x4 */
#define RK_OFF 196608     /* 4 x 256 B */
#define MB_OFF 197632     /* fK0 fK1 eK0 eK1 | fV0..3 | eV0..3 */
#define FSMEM_TOTAL 197760
#define NT (SS / BK)

__global__ __launch_bounds__(256, 1) void flash_mma_kernel(float* __restrict__ outp) {
    extern __shared__ char smem[];
    const uint32_t sb = smem_u32(smem);
    const uint32_t mb = sb + MB_OFF;
    const int t = threadIdx.x, w = t >> 5, lane = t & 31;
    const int b = blockIdx.x >> 5, qt = blockIdx.x & 31;
    const int qtok = b * SS + qt * BQ;
    const int m0 = w * 16;
    const int g = lane >> 3, rr = lane & 7;
    const int rowA = m0 + ((g & 1) << 3) + rr;  const int hA = g >> 1;
    const int rowB8 = ((g >> 1) << 3) + rr;      const int hB = g & 1;

    if (t == 0) {
        #pragma unroll
        for (int i = 0; i < 12; i++) MBAR_INIT(mb + i * 8, 256);
    }

    auto produce = [&](int p) {
        const int s2 = p & 1;
        const int s4 = p & 3;
        if (p >= 2) MBAR_WAIT(mb + 16 + s2 * 8, ((p >> 1) - 1) & 1);     // empty_K
        if (p >= 4) MBAR_WAIT(mb + 64 + s4 * 8, ((p >> 2) - 1) & 1);     // empty_V
        const int ktok = b * SS + p * BK;
        const uint32_t kb = sb + K_OFF + (uint32_t)s2 * KSTAGE;
        if (t < 16) cpasync16(sb + RK_OFF + s4 * 256 + t * 16, g_rk + ktok + t * 4);
        #pragma unroll
        for (int it = 0; it < 4; it++) {
            int lin = t + it * 256;
            int kr = lin >> 4, kc = lin & 15;
            cpasync16(kb + sw256(kr, kc), g_Kh + (size_t)(ktok + kr) * DD + kc * 8);
            cpasync16(kb + 16384 + sw256(kr, kc), g_Kl + (size_t)(ktok + kr) * DD + kc * 8);
        }
        CPA_MBAR_ARRIVE(mb + s2 * 8);                                    // full_K (+rk)
        const uint32_t vb = sb + V_OFF + (uint32_t)s4 * VSTAGE;
        #pragma unroll
        for (int it = 0; it < 4; it++) {
            int lin = t + it * 256;                  // 0..1023
            int vr = lin >> 3, vc = lin & 7;
            cpasync16(vb + sw128(vr, vc), g_Vth + (size_t)(b * DD + vr) * SS + p * BK + vc * 8);
        }
        CPA_MBAR_ARRIVE(mb + 32 + s4 * 8);                               // full_V
    };

    produce(0);
    produce(1);

    #pragma unroll
    for (int it = 0; it < 8; it++) {
        int lin = t + it * 256, r = lin >> 4, c = lin & 15;
        *reinterpret_cast<uint4*>(smem + QH_OFF + sw256(r, c)) =
            *reinterpret_cast<const uint4*>(g_Qh + (size_t)(qtok + r) * DD + c * 8);
        *reinterpret_cast<uint4*>(smem + QL_OFF + sw256(r, c)) =
            *reinterpret_cast<const uint4*>(g_Ql + (size_t)(qtok + r) * DD + c * 8);
    }
    const int r0g = qtok + m0 + (lane >> 2);
    const float rq0 = g_rq[r0g], rq1 = g_rq[r0g + 8];

    float o[16][4];
    #pragma unroll
    for (int i = 0; i < 16; i++) { o[i][0] = o[i][1] = o[i][2] = o[i][3] = 0.f; }
    float mr0 = -INFINITY, mr1 = -INFINITY, lr0 = 0.f, lr1 = 0.f;

    __syncthreads();   // Q visible + mbarriers initialized

    for (int kt = 0; kt < NT; kt++) {
        const int s2 = kt & 1;
        const int s4 = kt & 3;
        const uint32_t kb = sb + K_OFF + (uint32_t)s2 * KSTAGE;
        const uint32_t vb = sb + V_OFF + (uint32_t)s4 * VSTAGE;
        const float* smk = (const float*)(smem + RK_OFF + s4 * 256);

        MBAR_WAIT(mb + s2 * 8, (kt >> 1) & 1);          // full_K (+rk)

        // ---- S = Qc·Kc' (fp16 3-pass), 16x64 per warp ----
        float S[8][4];
        #pragma unroll
        for (int i = 0; i < 8; i++) { S[i][0] = S[i][1] = S[i][2] = S[i][3] = 0.f; }
        #pragma unroll
        for (int kc = 0; kc < 8; kc++) {
            uint32_t Ah[4], Al[4];
            ldsm4(Ah, sb + QH_OFF + sw256(rowA, kc * 2 + hA));
            ldsm4(Al, sb + QL_OFF + sw256(rowA, kc * 2 + hA));
            #pragma unroll
            for (int np = 0; np < 4; np++) {
                uint32_t Bh[4], Bl[4];
                ldsm4(Bh, kb + sw256(np * 16 + rowB8, kc * 2 + hB));
                ldsm4(Bl, kb + 16384 + sw256(np * 16 + rowB8, kc * 2 + hB));
                mma16816h(S[2 * np], Ah, Bh);     mma16816h(S[2 * np + 1], Ah, Bh + 2);
                mma16816h(S[2 * np], Ah, Bl);     mma16816h(S[2 * np + 1], Ah, Bl + 2);
                mma16816h(S[2 * np], Al, Bh);     mma16816h(S[2 * np + 1], Al, Bh + 2);
            }
        }
        MBAR_ARRIVE(mb + 16 + s2 * 8);                  // empty_K

        // ---- rank-1 + online softmax ----
        const int cbase = 2 * (lane & 3);
        float tm0 = -INFINITY, tm1 = -INFINITY;
        #pragma unroll
        for (int nt = 0; nt < 8; nt++) {
            float2 mk2 = *reinterpret_cast<const float2*>(&smk[nt * 8 + cbase]);
            S[nt][0] += rq0 * mk2.x; S[nt][1] += rq0 * mk2.y;
            S[nt][2] += rq1 * mk2.x; S[nt][3] += rq1 * mk2.y;
            tm0 = fmaxf(tm0, fmaxf(S[nt][0], S[nt][1]));
            tm1 = fmaxf(tm1, fmaxf(S[nt][2], S[nt][3]));
        }
        tm0 = fmaxf(tm0, __shfl_xor_sync(0xFFFFFFFFu, tm0, 1));
        tm0 = fmaxf(tm0, __shfl_xor_sync(0xFFFFFFFFu, tm0, 2));
        tm1 = fmaxf(tm1, __shfl_xor_sync(0xFFFFFFFFu, tm1, 1));
        tm1 = fmaxf(tm1, __shfl_xor_sync(0xFFFFFFFFu, tm1, 2));
        float nm0 = fmaxf(mr0, tm0), nm1 = fmaxf(mr1, tm1);
        float al0 = __expf(mr0 - nm0), al1 = __expf(mr1 - nm1);
        mr0 = nm0; mr1 = nm1;

        uint32_t PhL[8], PhH[8];
        float s0 = 0.f, s1 = 0.f;
        #pragma unroll
        for (int nt = 0; nt < 8; nt++) {
            float p0 = __expf(S[nt][0] - nm0), p1 = __expf(S[nt][1] - nm0);
            float p2 = __expf(S[nt][2] - nm1), p3 = __expf(S[nt][3] - nm1);
            s0 += p0 + p1; s1 += p2 + p3;
            PhL[nt] = pack_half2(p0, p1);
            PhH[nt] = pack_half2(p2, p3);
        }
        s0 += __shfl_xor_sync(0xFFFFFFFFu, s0, 1);
        s0 += __shfl_xor_sync(0xFFFFFFFFu, s0, 2);
        s1 += __shfl_xor_sync(0xFFFFFFFFu, s1, 1);
        s1 += __shfl_xor_sync(0xFFFFFFFFu, s1, 2);
        lr0 = lr0 * al0 + s0; lr1 = lr1 * al1 + s1;
        #pragma unroll
        for (int i = 0; i < 16; i++) { o[i][0] *= al0; o[i][1] *= al0; o[i][2] *= al1; o[i][3] *= al1; }

        MBAR_WAIT(mb + 32 + s4 * 8, (kt >> 2) & 1);     // full_V

        // ---- O += P·V (fp16 1-pass) ----
        #pragma unroll
        for (int kc = 0; kc < 4; kc++) {
            uint32_t Aph[4] = {PhL[2 * kc], PhH[2 * kc], PhL[2 * kc + 1], PhH[2 * kc + 1]};
            #pragma unroll
            for (int dp = 0; dp < 8; dp++) {
                uint32_t Bh[4];
                ldsm4(Bh, vb + sw128(dp * 16 + rowB8, kc * 2 + hB));
                mma16816h(o[2 * dp], Aph, Bh);
                mma16816h(o[2 * dp + 1], Aph, Bh + 2);
            }
        }
        MBAR_ARRIVE(mb + 64 + s4 * 8);                  // empty_V (+rk)

        if (kt + 2 < NT) produce(kt + 2);
    }

    const float inv0 = 1.f / lr0, inv1 = 1.f / lr1;
    #pragma unroll
    for (int nt = 0; nt < 16; nt++) {
        int col = nt * 8 + 2 * (lane & 3);
        *reinterpret_cast<float2*>(outp + (size_t)r0g * DD + col) =
            make_float2(o[nt][0] * inv0, o[nt][1] * inv0);
        *reinterpret_cast<float2*>(outp + (size_t)(r0g + 8) * DD + col) =
            make_float2(o[nt][2] * inv1, o[nt][3] * inv1);
    }
}

extern "C" void kernel_launch(void* const* d_in, const int* in_sizes, int n_in,
                              void* d_out, int out_size) {
    const float* x  = (const float*)d_in[0];
    const float* wq = (const float*)d_in[2];
    const float* wk = (const float*)d_in[3];
    const float* wv = (const float*)d_in[4];
    float* out = (float*)d_out;

    cudaFuncSetAttribute(proj_kernel, cudaFuncAttributeMaxDynamicSharedMemorySize, PSMEM);
    cudaFuncSetAttribute(flash_mma_kernel, cudaFuncAttributeMaxDynamicSharedMemorySize, FSMEM_TOTAL);

    proj_kernel<<<dim3(128, 3), 256, PSMEM>>>(x, wq, wk, wv);
    flash_mma_kernel<<<BB * (SS / BQ), 256, FSMEM_TOTAL>>>(out);
}

// round 15
// speedup vs baseline: 1.5565x; 1.0027x over previous
#include <cuda_runtime.h>
#include <cuda_bf16.h>
#include <cuda_fp16.h>
#include <math.h>
#include <stdint.h>

#define DD 128
#define SS 4096
#define BB 4

__device__ __half g_Qh[BB * SS * DD];
__device__ __half g_Ql[BB * SS * DD];
__device__ __half g_Kh[BB * SS * DD];
__device__ __half g_Kl[BB * SS * DD];
__device__ __half g_Vth[BB * DD * SS];   // [b*128+d][token], fp16, unsplit
__device__ float g_rq[BB * SS];
__device__ float g_rk[BB * SS];

// ---- PTX helpers (arch-portable) ----
__device__ __forceinline__ uint32_t smem_u32(const void* p) {
    uint32_t a;
    asm("{ .reg .u64 t; cvta.to.shared.u64 t, %1; cvt.u32.u64 %0, t; }" : "=r"(a) : "l"(p));
    return a;
}
__device__ __forceinline__ void ldsm4(uint32_t* d, uint32_t addr) {
    asm volatile("ldmatrix.sync.aligned.m8n8.x4.shared.b16 {%0,%1,%2,%3}, [%4];"
                 : "=r"(d[0]), "=r"(d[1]), "=r"(d[2]), "=r"(d[3]) : "r"(addr));
}
__device__ __forceinline__ void mma16816h(float* c, const uint32_t* a, const uint32_t* b) {
    asm volatile("mma.sync.aligned.m16n8k16.row.col.f32.f16.f16.f32 "
                 "{%0,%1,%2,%3}, {%4,%5,%6,%7}, {%8,%9}, {%0,%1,%2,%3};"
                 : "+f"(c[0]), "+f"(c[1]), "+f"(c[2]), "+f"(c[3])
                 : "r"(a[0]), "r"(a[1]), "r"(a[2]), "r"(a[3]), "r"(b[0]), "r"(b[1]));
}
__device__ __forceinline__ uint32_t pack_half2(float lo, float hi) {
    uint32_t r;
    asm("cvt.rn.f16x2.f32 %0, %1, %2;" : "=r"(r) : "f"(hi), "f"(lo));
    return r;
}
__device__ __forceinline__ void cpasync16(uint32_t s, const void* g) {
    asm volatile("cp.async.cg.shared.global [%0], [%1], 16;" :: "r"(s), "l"(g));
}
#define MBAR_INIT(a, c) asm volatile("mbarrier.init.shared.b64 [%0], %1;" :: "r"((uint32_t)(a)), "r"((uint32_t)(c)) : "memory")
#define MBAR_ARRIVE(a)  asm volatile("mbarrier.arrive.shared.b64 _, [%0];" :: "r"((uint32_t)(a)) : "memory")
#define CPA_MBAR_ARRIVE(a) asm volatile("cp.async.mbarrier.arrive.noinc.shared.b64 [%0];" :: "r"((uint32_t)(a)) : "memory")
#define MBAR_WAIT(a, par) do { uint32_t _m=(uint32_t)(a), _p=(uint32_t)(par), _d; \
    asm volatile("{\n\t.reg .pred p;\n\tmbarrier.try_wait.parity.acquire.cta.shared::cta.b64 p,[%1],%2;\n\tselp.b32 %0,1,0,p;\n\t}" : "=r"(_d) : "r"(_m), "r"(_p) : "memory"); \
    if (!_d) asm volatile("{\n\t.reg .pred P1;\n\tWL_%=:\n\tmbarrier.try_wait.parity.acquire.cta.shared::cta.b64 P1,[%0],%1,0x989680;\n\t@P1 bra.uni WD_%=;\n\tbra.uni WL_%=;\n\tWD_%=:\n\t}" :: "r"(_m), "r"(_p) : "memory"); } while (0)

__device__ __forceinline__ uint32_t sw256(int r, int c16) {   // 256B rows
    return (uint32_t)(r * 256 + (((c16 & 8) | ((c16 & 7) ^ (r & 7))) << 4));
}
__device__ __forceinline__ uint32_t sw128(int r, int c8) {    // 128B rows
    return (uint32_t)(r * 128 + (((c8 ^ r) & 7) << 4));
}

// ================= fused QKV projection + center/split/transpose =============
#define PA_H 0
#define PA_L 32768
#define PB_H 65536
#define PB_L 98304
#define PC_OFF 131072
#define PR_OFF (PC_OFF + 128 * 132 * 4)
#define PSMEM  (PR_OFF + 1024)

__global__ __launch_bounds__(256, 1) void proj_kernel(const float* __restrict__ xg,
                                                      const float* __restrict__ wq,
                                                      const float* __restrict__ wk,
                                                      const float* __restrict__ wv) {
    extern __shared__ char smem[];
    const uint32_t sb = smem_u32(smem);
    float* tileC = (float*)(smem + PC_OFF);
    float* rmean = (float*)(smem + PR_OFF);
    const int t = threadIdx.x, w = t >> 5, lane = t & 31;
    const int tile = blockIdx.x, proj = blockIdx.y;
    const int tok0 = tile * 128;
    const int b = tok0 >> 12, s0 = tok0 & (SS - 1);
    const float* W = (proj == 0) ? wq : (proj == 1) ? wk : wv;
    const float SCALE = 0.08838834764831845f;

    #pragma unroll
    for (int it = 0; it < 8; it++) {
        int lin = t + it * 256;
        int r = lin >> 4, c16 = lin & 15;
        const float* src = xg + (size_t)(tok0 + r) * DD + c16 * 8;
        float4 v0 = *reinterpret_cast<const float4*>(src);
        float4 v1 = *reinterpret_cast<const float4*>(src + 4);
        __half2 h0 = __floats2half2_rn(v0.x, v0.y), h1 = __floats2half2_rn(v0.z, v0.w);
        __half2 h2 = __floats2half2_rn(v1.x, v1.y), h3 = __floats2half2_rn(v1.z, v1.w);
        float2 f0 = __half22float2(h0), f1 = __half22float2(h1);
        float2 f2 = __half22float2(h2), f3 = __half22float2(h3);
        __half2 l0 = __floats2half2_rn(v0.x - f0.x, v0.y - f0.y);
        __half2 l1 = __floats2half2_rn(v0.z - f1.x, v0.w - f1.y);
        __half2 l2 = __floats2half2_rn(v1.x - f2.x, v1.y - f2.y);
        __half2 l3 = __floats2half2_rn(v1.z - f3.x, v1.w - f3.y);
        uint4 hv = make_uint4(*(uint32_t*)&h0, *(uint32_t*)&h1, *(uint32_t*)&h2, *(uint32_t*)&h3);
        uint4 lv = make_uint4(*(uint32_t*)&l0, *(uint32_t*)&l1, *(uint32_t*)&l2, *(uint32_t*)&l3);
        *reinterpret_cast<uint4*>(smem + PA_H + sw256(r, c16)) = hv;
        *reinterpret_cast<uint4*>(smem + PA_L + sw256(r, c16)) = lv;
    }
    #pragma unroll
    for (int it = 0; it < 8; it++) {
        int lin = t + it * 256;
        int d = lin >> 4, c16 = lin & 15;
        const float* src = W + (size_t)d * DD + c16 * 8;
        float wv[8];
        *reinterpret_cast<float4*>(wv) = *reinterpret_cast<const float4*>(src);
        *reinterpret_cast<float4*>(wv + 4) = *reinterpret_cast<const float4*>(src + 4);
        #pragma unroll
        for (int j = 0; j < 8; j++) {
            int e = c16 * 8 + j;
            __half h = __float2half_rn(wv[j]);
            __half l = __float2half_rn(wv[j] - __half2float(h));
            uint32_t off = sw256(e, d >> 3) + (d & 7) * 2;
            *reinterpret_cast<__half*>(smem + PB_H + off) = h;
            *reinterpret_cast<__half*>(smem + PB_L + off) = l;
        }
    }
    __syncthreads();

    const int m0 = w * 16;
    const int g = lane >> 3, rr = lane & 7;
    const int rowA = m0 + ((g & 1) << 3) + rr;  const int hA = g >> 1;
    const int rowB8 = ((g >> 1) << 3) + rr;      const int hB = g & 1;

    float C[16][4];
    #pragma unroll
    for (int i = 0; i < 16; i++) { C[i][0] = C[i][1] = C[i][2] = C[i][3] = 0.f; }
    #pragma unroll
    for (int kc = 0; kc < 8; kc++) {
        uint32_t Ah[4], Al[4];
        ldsm4(Ah, sb + PA_H + sw256(rowA, kc * 2 + hA));
        ldsm4(Al, sb + PA_L + sw256(rowA, kc * 2 + hA));
        #pragma unroll
        for (int np = 0; np < 8; np++) {
            uint32_t Bh[4], Bl[4];
            ldsm4(Bh, sb + PB_H + sw256(np * 16 + rowB8, kc * 2 + hB));
            ldsm4(Bl, sb + PB_L + sw256(np * 16 + rowB8, kc * 2 + hB));
            mma16816h(C[2 * np], Ah, Bh);     mma16816h(C[2 * np + 1], Ah, Bh + 2);
            mma16816h(C[2 * np], Ah, Bl);     mma16816h(C[2 * np + 1], Ah, Bl + 2);
            mma16816h(C[2 * np], Al, Bh);     mma16816h(C[2 * np + 1], Al, Bh + 2);
        }
    }
    __syncthreads();

    const int lr = lane >> 2, lc = 2 * (lane & 3);
    #pragma unroll
    for (int np = 0; np < 8; np++) {
        #pragma unroll
        for (int nn = 0; nn < 2; nn++) {
            int c0 = np * 16 + nn * 8 + lc;
            float* p0 = tileC + (m0 + lr) * 132 + c0;
            float* p1 = tileC + (m0 + lr + 8) * 132 + c0;
            p0[0] = C[np * 2 + nn][0]; p0[1] = C[np * 2 + nn][1];
            p1[0] = C[np * 2 + nn][2]; p1[1] = C[np * 2 + nn][3];
        }
    }
    __syncthreads();

    if (proj < 2) {
        const int r = t >> 1, part = t & 1;
        float s = 0.f;
        #pragma unroll
        for (int j = 0; j < 16; j++) {
            float4 v = *reinterpret_cast<float4*>(tileC + r * 132 + part * 64 + j * 4);
            s += v.x + v.y + v.z + v.w;
        }
        s += __shfl_xor_sync(0xFFFFFFFFu, s, 1);
        if (proj == 0) {
            float rq = s * SCALE;
            if (part == 0) { rmean[r] = rq * (1.f / 128.f); g_rq[tok0 + r] = rq; }
        } else {
            float mk = s * (1.f / 128.f);
            if (part == 0) { rmean[r] = mk; g_rk[tok0 + r] = mk; }
        }
        __syncthreads();
        const float mu = rmean[r];
        __half* gh = (proj == 0) ? g_Qh : g_Kh;
        __half* gl = (proj == 0) ? g_Ql : g_Kl;
        const float fac = (proj == 0) ? SCALE : 1.f;
        #pragma unroll
        for (int j8 = 0; j8 < 8; j8++) {
            int c = part * 64 + j8 * 8;
            __align__(16) __half hs[8], ls[8];
            #pragma unroll
            for (int j = 0; j < 8; j++) {
                float v = tileC[r * 132 + c + j] * fac - mu;
                __half h = __float2half_rn(v);
                hs[j] = h; ls[j] = __float2half_rn(v - __half2float(h));
            }
            size_t ob = (size_t)(tok0 + r) * DD + c;
            *reinterpret_cast<uint4*>(&gh[ob]) = *reinterpret_cast<uint4*>(hs);
            *reinterpret_cast<uint4*>(&gl[ob]) = *reinterpret_cast<uint4*>(ls);
        }
    } else {
        const int od = t >> 1, seg = t & 1;
        #pragma unroll
        for (int j8 = 0; j8 < 8; j8++) {
            __align__(16) __half hs[8];
            #pragma unroll
            for (int j = 0; j < 8; j++)
                hs[j] = __float2half_rn(tileC[(seg * 64 + j8 * 8 + j) * 132 + od]);
            size_t ob = (size_t)(b * DD + od) * SS + s0 + seg * 64 + j8 * 8;
            *reinterpret_cast<uint4*>(&g_Vth[ob]) = *reinterpret_cast<uint4*>(hs);
        }
    }
}

// ---- flash v5: fp16 3+1 passes; S double-buffer (QK one tile ahead) ----
#define BQ 128
#define BK 64
#define QH_OFF 0
#define QL_OFF 32768
#define K_OFF  65536
#define KSTAGE 32768      /* [Kh 16K | Kl 16K] x2 */
#define V_OFF  131072
#define VSTAGE 16384      /* [Vh 16K] x4 */
#define RK_OFF 196608     /* 4 x 256 B */
#define MB_OFF 197632     /* fK0 fK1 eK0 eK1 | fV0..3 | eV0..3 */
#define FSMEM_TOTAL 197760
#define NT (SS / BK)

__global__ __launch_bounds__(256, 1) void flash_mma_kernel(float* __restrict__ outp) {
    extern __shared__ char smem[];
    const uint32_t sb = smem_u32(smem);
    const uint32_t mb = sb + MB_OFF;
    const int t = threadIdx.x, w = t >> 5, lane = t & 31;
    const int b = blockIdx.x >> 5, qt = blockIdx.x & 31;
    const int qtok = b * SS + qt * BQ;
    const int m0 = w * 16;
    const int g = lane >> 3, rr = lane & 7;
    const int rowA = m0 + ((g & 1) << 3) + rr;  const int hA = g >> 1;
    const int rowB8 = ((g >> 1) << 3) + rr;      const int hB = g & 1;

    if (t == 0) {
        #pragma unroll
        for (int i = 0; i < 12; i++) MBAR_INIT(mb + i * 8, 256);
    }

    auto produce = [&](int p) {
        const int s2 = p & 1;
        const int s4 = p & 3;
        if (p >= 2) MBAR_WAIT(mb + 16 + s2 * 8, ((p >> 1) - 1) & 1);     // empty_K
        if (p >= 4) MBAR_WAIT(mb + 64 + s4 * 8, ((p >> 2) - 1) & 1);     // empty_V
        const int ktok = b * SS + p * BK;
        const uint32_t kb = sb + K_OFF + (uint32_t)s2 * KSTAGE;
        if (t < 16) cpasync16(sb + RK_OFF + s4 * 256 + t * 16, g_rk + ktok + t * 4);
        #pragma unroll
        for (int it = 0; it < 4; it++) {
            int lin = t + it * 256;
            int kr = lin >> 4, kc = lin & 15;
            cpasync16(kb + sw256(kr, kc), g_Kh + (size_t)(ktok + kr) * DD + kc * 8);
            cpasync16(kb + 16384 + sw256(kr, kc), g_Kl + (size_t)(ktok + kr) * DD + kc * 8);
        }
        CPA_MBAR_ARRIVE(mb + s2 * 8);                                    // full_K (+rk)
        const uint32_t vb = sb + V_OFF + (uint32_t)s4 * VSTAGE;
        #pragma unroll
        for (int it = 0; it < 4; it++) {
            int lin = t + it * 256;
            int vr = lin >> 3, vc = lin & 7;
            cpasync16(vb + sw128(vr, vc), g_Vth + (size_t)(b * DD + vr) * SS + p * BK + vc * 8);
        }
        CPA_MBAR_ARRIVE(mb + 32 + s4 * 8);                               // full_V
    };

    produce(0);
    produce(1);

    #pragma unroll
    for (int it = 0; it < 8; it++) {
        int lin = t + it * 256, r = lin >> 4, c = lin & 15;
        *reinterpret_cast<uint4*>(smem + QH_OFF + sw256(r, c)) =
            *reinterpret_cast<const uint4*>(g_Qh + (size_t)(qtok + r) * DD + c * 8);
        *reinterpret_cast<uint4*>(smem + QL_OFF + sw256(r, c)) =
            *reinterpret_cast<const uint4*>(g_Ql + (size_t)(qtok + r) * DD + c * 8);
    }
    const int r0g = qtok + m0 + (lane >> 2);
    const float rq0 = g_rq[r0g], rq1 = g_rq[r0g + 8];

    float o[16][4];
    #pragma unroll
    for (int i = 0; i < 16; i++) { o[i][0] = o[i][1] = o[i][2] = o[i][3] = 0.f; }
    float mr0 = -INFINITY, mr1 = -INFINITY, lr0 = 0.f, lr1 = 0.f;
    float SA[8][4], SB[8][4];
    uint32_t PhL[8], PhH[8];

    // QK into given S buffer for tile p (wait fK + arrive eK inside)
    auto qk_tile = [&](float (&S)[8][4], int p) {
        const int s2 = p & 1;
        MBAR_WAIT(mb + s2 * 8, (p >> 1) & 1);
        const uint32_t kb = sb + K_OFF + (uint32_t)s2 * KSTAGE;
        #pragma unroll
        for (int i = 0; i < 8; i++) { S[i][0] = S[i][1] = S[i][2] = S[i][3] = 0.f; }
        #pragma unroll
        for (int kc = 0; kc < 8; kc++) {
            uint32_t Ah[4], Al[4];
            ldsm4(Ah, sb + QH_OFF + sw256(rowA, kc * 2 + hA));
            ldsm4(Al, sb + QL_OFF + sw256(rowA, kc * 2 + hA));
            #pragma unroll
            for (int np = 0; np < 4; np++) {
                uint32_t Bh[4], Bl[4];
                ldsm4(Bh, kb + sw256(np * 16 + rowB8, kc * 2 + hB));
                ldsm4(Bl, kb + 16384 + sw256(np * 16 + rowB8, kc * 2 + hB));
                mma16816h(S[2 * np], Ah, Bh);     mma16816h(S[2 * np + 1], Ah, Bh + 2);
                mma16816h(S[2 * np], Ah, Bl);     mma16816h(S[2 * np + 1], Ah, Bl + 2);
                mma16816h(S[2 * np], Al, Bh);     mma16816h(S[2 * np + 1], Al, Bh + 2);
            }
        }
        MBAR_ARRIVE(mb + 16 + s2 * 8);
    };

    // softmax on S buffer for tile p -> PhL/PhH + o rescale + l update
    auto softmax_tile = [&](float (&S)[8][4], int p) {
        const float* smk = (const float*)(smem + RK_OFF + (p & 3) * 256);
        const int cbase = 2 * (lane & 3);
        float tm0 = -INFINITY, tm1 = -INFINITY;
        #pragma unroll
        for (int nt = 0; nt < 8; nt++) {
            float2 mk2 = *reinterpret_cast<const float2*>(&smk[nt * 8 + cbase]);
            S[nt][0] += rq0 * mk2.x; S[nt][1] += rq0 * mk2.y;
            S[nt][2] += rq1 * mk2.x; S[nt][3] += rq1 * mk2.y;
            tm0 = fmaxf(tm0, fmaxf(S[nt][0], S[nt][1]));
            tm1 = fmaxf(tm1, fmaxf(S[nt][2], S[nt][3]));
        }
        tm0 = fmaxf(tm0, __shfl_xor_sync(0xFFFFFFFFu, tm0, 1));
        tm0 = fmaxf(tm0, __shfl_xor_sync(0xFFFFFFFFu, tm0, 2));
        tm1 = fmaxf(tm1, __shfl_xor_sync(0xFFFFFFFFu, tm1, 1));
        tm1 = fmaxf(tm1, __shfl_xor_sync(0xFFFFFFFFu, tm1, 2));
        float nm0 = fmaxf(mr0, tm0), nm1 = fmaxf(mr1, tm1);
        float al0 = __expf(mr0 - nm0), al1 = __expf(mr1 - nm1);
        mr0 = nm0; mr1 = nm1;
        float s0 = 0.f, s1 = 0.f;
        #pragma unroll
        for (int nt = 0; nt < 8; nt++) {
            float p0 = __expf(S[nt][0] - nm0), p1 = __expf(S[nt][1] - nm0);
            float p2 = __expf(S[nt][2] - nm1), p3 = __expf(S[nt][3] - nm1);
            s0 += p0 + p1; s1 += p2 + p3;
            PhL[nt] = pack_half2(p0, p1);
            PhH[nt] = pack_half2(p2, p3);
        }
        s0 += __shfl_xor_sync(0xFFFFFFFFu, s0, 1);
        s0 += __shfl_xor_sync(0xFFFFFFFFu, s0, 2);
        s1 += __shfl_xor_sync(0xFFFFFFFFu, s1, 1);
        s1 += __shfl_xor_sync(0xFFFFFFFFu, s1, 2);
        lr0 = lr0 * al0 + s0; lr1 = lr1 * al1 + s1;
        if (al0 != 1.f || al1 != 1.f) {
            #pragma unroll
            for (int i = 0; i < 16; i++) { o[i][0] *= al0; o[i][1] *= al0; o[i][2] *= al1; o[i][3] *= al1; }
        }
    };

    auto pv_tile = [&](int p) {
        const int s4 = p & 3;
        MBAR_WAIT(mb + 32 + s4 * 8, (p >> 2) & 1);
        const uint32_t vb = sb + V_OFF + (uint32_t)s4 * VSTAGE;
        #pragma unroll
        for (int kc = 0; kc < 4; kc++) {
            uint32_t Aph[4] = {PhL[2 * kc], PhH[2 * kc], PhL[2 * kc + 1], PhH[2 * kc + 1]};
            #pragma unroll
            for (int dp = 0; dp < 8; dp++) {
                uint32_t Bh[4];
                ldsm4(Bh, vb + sw128(dp * 16 + rowB8, kc * 2 + hB));
                mma16816h(o[2 * dp], Aph, Bh);
                mma16816h(o[2 * dp + 1], Aph, Bh + 2);
            }
        }
        MBAR_ARRIVE(mb + 64 + s4 * 8);
    };

    __syncthreads();   // Q visible + mbarriers initialized
    qk_tile(SA, 0);    // prologue: S for tile 0

    for (int kt = 0; kt < NT; kt += 2) {
        // body A: preload S(kt+1), consume S(kt)
        qk_tile(SB, kt + 1);          // always valid: kt+1 <= NT-1
        if (kt + 2 < NT) produce(kt + 2);
        softmax_tile(SA, kt);         // MUFU overlaps SB's MMA shadow
        pv_tile(kt);
        // body B: preload S(kt+2), consume S(kt+1)
        if (kt + 2 < NT) qk_tile(SA, kt + 2);
        if (kt + 3 < NT) produce(kt + 3);
        softmax_tile(SB, kt + 1);
        pv_tile(kt + 1);
    }

    const float inv0 = 1.f / lr0, inv1 = 1.f / lr1;
    #pragma unroll
    for (int nt = 0; nt < 16; nt++) {
        int col = nt * 8 + 2 * (lane & 3);
        *reinterpret_cast<float2*>(outp + (size_t)r0g * DD + col) =
            make_float2(o[nt][0] * inv0, o[nt][1] * inv0);
        *reinterpret_cast<float2*>(outp + (size_t)(r0g + 8) * DD + col) =
            make_float2(o[nt][2] * inv1, o[nt][3] * inv1);
    }
}

extern "C" void kernel_launch(void* const* d_in, const int* in_sizes, int n_in,
                              void* d_out, int out_size) {
    const float* x  = (const float*)d_in[0];
    const float* wq = (const float*)d_in[2];
    const float* wk = (const float*)d_in[3];
    const float* wv = (const float*)d_in[4];
    float* out = (float*)d_out;

    cudaFuncSetAttribute(proj_kernel, cudaFuncAttributeMaxDynamicSharedMemorySize, PSMEM);
    cudaFuncSetAttribute(flash_mma_kernel, cudaFuncAttributeMaxDynamicSharedMemorySize, FSMEM_TOTAL);

    proj_kernel<<<dim3(128, 3), 256, PSMEM>>>(x, wq, wk, wv);
    flash_mma_kernel<<<BB * (SS / BQ), 256, FSMEM_TOTAL>>>(out);
}

// round 16
// speedup vs baseline: 1.7573x; 1.1290x over previous
#include <cuda_runtime.h>
#include <cuda_bf16.h>
#include <cuda_fp16.h>
#include <math.h>
#include <stdint.h>

#define DD 128
#define SS 4096
#define BB 4

__device__ __half g_Qh[BB * SS * DD];
__device__ __half g_Ql[BB * SS * DD];
__device__ __half g_Kh[BB * SS * DD];
__device__ __half g_Kl[BB * SS * DD];
__device__ __half g_Vth[BB * DD * SS];   // [b*128+d][token], fp16, unsplit
__device__ float g_rq[BB * SS];
__device__ float g_rk[BB * SS];

// ---- PTX helpers (arch-portable) ----
__device__ __forceinline__ uint32_t smem_u32(const void* p) {
    uint32_t a;
    asm("{ .reg .u64 t; cvta.to.shared.u64 t, %1; cvt.u32.u64 %0, t; }" : "=r"(a) : "l"(p));
    return a;
}
__device__ __forceinline__ void ldsm4(uint32_t* d, uint32_t addr) {
    asm volatile("ldmatrix.sync.aligned.m8n8.x4.shared.b16 {%0,%1,%2,%3}, [%4];"
                 : "=r"(d[0]), "=r"(d[1]), "=r"(d[2]), "=r"(d[3]) : "r"(addr));
}
__device__ __forceinline__ void ldsm4t(uint32_t* d, uint32_t addr) {
    asm volatile("ldmatrix.sync.aligned.m8n8.x4.trans.shared.b16 {%0,%1,%2,%3}, [%4];"
                 : "=r"(d[0]), "=r"(d[1]), "=r"(d[2]), "=r"(d[3]) : "r"(addr));
}
__device__ __forceinline__ void mma16816h(float* c, const uint32_t* a, const uint32_t* b) {
    asm volatile("mma.sync.aligned.m16n8k16.row.col.f32.f16.f16.f32 "
                 "{%0,%1,%2,%3}, {%4,%5,%6,%7}, {%8,%9}, {%0,%1,%2,%3};"
                 : "+f"(c[0]), "+f"(c[1]), "+f"(c[2]), "+f"(c[3])
                 : "r"(a[0]), "r"(a[1]), "r"(a[2]), "r"(a[3]), "r"(b[0]), "r"(b[1]));
}
__device__ __forceinline__ uint32_t pack_half2(float lo, float hi) {
    uint32_t r;
    asm("cvt.rn.f16x2.f32 %0, %1, %2;" : "=r"(r) : "f"(hi), "f"(lo));
    return r;
}
__device__ __forceinline__ void cpasync16(uint32_t s, const void* g) {
    asm volatile("cp.async.cg.shared.global [%0], [%1], 16;" :: "r"(s), "l"(g));
}
#define MBAR_INIT(a, c) asm volatile("mbarrier.init.shared.b64 [%0], %1;" :: "r"((uint32_t)(a)), "r"((uint32_t)(c)) : "memory")
#define MBAR_ARRIVE(a)  asm volatile("mbarrier.arrive.shared.b64 _, [%0];" :: "r"((uint32_t)(a)) : "memory")
#define CPA_MBAR_ARRIVE(a) asm volatile("cp.async.mbarrier.arrive.noinc.shared.b64 [%0];" :: "r"((uint32_t)(a)) : "memory")
#define MBAR_WAIT(a, par) do { uint32_t _m=(uint32_t)(a), _p=(uint32_t)(par), _d; \
    asm volatile("{\n\t.reg .pred p;\n\tmbarrier.try_wait.parity.acquire.cta.shared::cta.b64 p,[%1],%2;\n\tselp.b32 %0,1,0,p;\n\t}" : "=r"(_d) : "r"(_m), "r"(_p) : "memory"); \
    if (!_d) asm volatile("{\n\t.reg .pred P1;\n\tWL_%=:\n\tmbarrier.try_wait.parity.acquire.cta.shared::cta.b64 P1,[%0],%1,0x989680;\n\t@P1 bra.uni WD_%=;\n\tbra.uni WL_%=;\n\tWD_%=:\n\t}" :: "r"(_m), "r"(_p) : "memory"); } while (0)

__device__ __forceinline__ uint32_t sw256(int r, int c16) {   // 256B rows
    return (uint32_t)(r * 256 + (((c16 & 8) | ((c16 & 7) ^ (r & 7))) << 4));
}
__device__ __forceinline__ uint32_t sw128(int r, int c8) {    // 128B rows
    return (uint32_t)(r * 128 + (((c8 ^ r) & 7) << 4));
}

// ============ fused QKV projection v2: ldsm.trans B, regfile epilogue =========
#define PA_H 0
#define PA_L 32768
#define PB_H 65536
#define PB_L 98304
#define PC_OFF 131072                  /* fp32 tile [128][132] — V blocks only */
#define PSMEM  (PC_OFF + 128 * 132 * 4)

__global__ __launch_bounds__(256, 1) void proj_kernel(const float* __restrict__ xg,
                                                      const float* __restrict__ wq,
                                                      const float* __restrict__ wk,
                                                      const float* __restrict__ wv) {
    extern __shared__ char smem[];
    const uint32_t sb = smem_u32(smem);
    float* tileC = (float*)(smem + PC_OFF);
    const int t = threadIdx.x, w = t >> 5, lane = t & 31;
    const int tile = blockIdx.x, proj = blockIdx.y;
    const int tok0 = tile * 128;
    const int b = tok0 >> 12, s0 = tok0 & (SS - 1);
    const float* W = (proj == 0) ? wq : (proj == 1) ? wk : wv;
    const float SCALE = 0.08838834764831845f;

    // x tile -> fp16 h/l smem (swizzled, vectorized), W -> row-major h/l smem
    #pragma unroll
    for (int it = 0; it < 8; it++) {
        int lin = t + it * 256;
        int r = lin >> 4, c16 = lin & 15;
        {
            const float* src = xg + (size_t)(tok0 + r) * DD + c16 * 8;
            float4 v0 = *reinterpret_cast<const float4*>(src);
            float4 v1 = *reinterpret_cast<const float4*>(src + 4);
            __half2 h0 = __floats2half2_rn(v0.x, v0.y), h1 = __floats2half2_rn(v0.z, v0.w);
            __half2 h2 = __floats2half2_rn(v1.x, v1.y), h3 = __floats2half2_rn(v1.z, v1.w);
            float2 f0 = __half22float2(h0), f1 = __half22float2(h1);
            float2 f2 = __half22float2(h2), f3 = __half22float2(h3);
            __half2 l0 = __floats2half2_rn(v0.x - f0.x, v0.y - f0.y);
            __half2 l1 = __floats2half2_rn(v0.z - f1.x, v0.w - f1.y);
            __half2 l2 = __floats2half2_rn(v1.x - f2.x, v1.y - f2.y);
            __half2 l3 = __floats2half2_rn(v1.z - f3.x, v1.w - f3.y);
            uint4 hv = make_uint4(*(uint32_t*)&h0, *(uint32_t*)&h1, *(uint32_t*)&h2, *(uint32_t*)&h3);
            uint4 lv = make_uint4(*(uint32_t*)&l0, *(uint32_t*)&l1, *(uint32_t*)&l2, *(uint32_t*)&l3);
            *reinterpret_cast<uint4*>(smem + PA_H + sw256(r, c16)) = hv;
            *reinterpret_cast<uint4*>(smem + PA_L + sw256(r, c16)) = lv;
        }
        {
            const float* src = W + (size_t)r * DD + c16 * 8;   // row r of W (k-major)
            float4 v0 = *reinterpret_cast<const float4*>(src);
            float4 v1 = *reinterpret_cast<const float4*>(src + 4);
            __half2 h0 = __floats2half2_rn(v0.x, v0.y), h1 = __floats2half2_rn(v0.z, v0.w);
            __half2 h2 = __floats2half2_rn(v1.x, v1.y), h3 = __floats2half2_rn(v1.z, v1.w);
            float2 f0 = __half22float2(h0), f1 = __half22float2(h1);
            float2 f2 = __half22float2(h2), f3 = __half22float2(h3);
            __half2 l0 = __floats2half2_rn(v0.x - f0.x, v0.y - f0.y);
            __half2 l1 = __floats2half2_rn(v0.z - f1.x, v0.w - f1.y);
            __half2 l2 = __floats2half2_rn(v1.x - f2.x, v1.y - f2.y);
            __half2 l3 = __floats2half2_rn(v1.z - f3.x, v1.w - f3.y);
            uint4 hv = make_uint4(*(uint32_t*)&h0, *(uint32_t*)&h1, *(uint32_t*)&h2, *(uint32_t*)&h3);
            uint4 lv = make_uint4(*(uint32_t*)&l0, *(uint32_t*)&l1, *(uint32_t*)&l2, *(uint32_t*)&l3);
            *reinterpret_cast<uint4*>(smem + PB_H + sw256(r, c16)) = hv;
            *reinterpret_cast<uint4*>(smem + PB_L + sw256(r, c16)) = lv;
        }
    }
    __syncthreads();

    const int m0 = w * 16;
    const int g = lane >> 3, rr = lane & 7;
    const int rowA = m0 + ((g & 1) << 3) + rr;  const int hA = g >> 1;
    // ldsm.trans B: row = k-row, chunk = n-octet;  m%2 selects k-octet, m/2 selects n-octet
    const int rowBt = ((g & 1) << 3) + rr;       const int cBt = g >> 1;

    float C[16][4];
    #pragma unroll
    for (int i = 0; i < 16; i++) { C[i][0] = C[i][1] = C[i][2] = C[i][3] = 0.f; }
    #pragma unroll
    for (int kc = 0; kc < 8; kc++) {
        uint32_t Ah[4], Al[4];
        ldsm4(Ah, sb + PA_H + sw256(rowA, kc * 2 + hA));
        ldsm4(Al, sb + PA_L + sw256(rowA, kc * 2 + hA));
        #pragma unroll
        for (int np = 0; np < 8; np++) {
            uint32_t Bh[4], Bl[4];
            ldsm4t(Bh, sb + PB_H + sw256(kc * 16 + rowBt, np * 2 + cBt));
            ldsm4t(Bl, sb + PB_L + sw256(kc * 16 + rowBt, np * 2 + cBt));
            mma16816h(C[2 * np], Ah, Bh);     mma16816h(C[2 * np + 1], Ah, Bh + 2);
            mma16816h(C[2 * np], Ah, Bl);     mma16816h(C[2 * np + 1], Ah, Bl + 2);
            mma16816h(C[2 * np], Al, Bh);     mma16816h(C[2 * np + 1], Al, Bh + 2);
        }
    }

    if (proj < 2) {
        // ---- register-file epilogue: rowsum -> center -> h/l split -> global ----
        float part0 = 0.f, part1 = 0.f;
        #pragma unroll
        for (int nt = 0; nt < 16; nt++) {
            part0 += C[nt][0] + C[nt][1];
            part1 += C[nt][2] + C[nt][3];
        }
        part0 += __shfl_xor_sync(0xFFFFFFFFu, part0, 1);
        part0 += __shfl_xor_sync(0xFFFFFFFFu, part0, 2);
        part1 += __shfl_xor_sync(0xFFFFFFFFu, part1, 1);
        part1 += __shfl_xor_sync(0xFFFFFFFFu, part1, 2);
        const float fac = (proj == 0) ? SCALE : 1.f;
        const float sum0 = part0 * fac, sum1 = part1 * fac;
        const float mu0 = sum0 * (1.f / 128.f), mu1 = sum1 * (1.f / 128.f);
        const int row0 = tok0 + m0 + (lane >> 2);
        if ((lane & 3) == 0) {
            if (proj == 0) { g_rq[row0] = sum0; g_rq[row0 + 8] = sum1; }
            else           { g_rk[row0] = mu0;  g_rk[row0 + 8] = mu1;  }
        }
        __half* gh = (proj == 0) ? g_Qh : g_Kh;
        __half* gl = (proj == 0) ? g_Ql : g_Kl;
        const int lc = 2 * (lane & 3);
        #pragma unroll
        for (int nt = 0; nt < 16; nt++) {
            int col = nt * 8 + lc;
            float v0 = C[nt][0] * fac - mu0, v1 = C[nt][1] * fac - mu0;
            float v2 = C[nt][2] * fac - mu1, v3 = C[nt][3] * fac - mu1;
            float h0 = __half2float(__float2half_rn(v0)), h1 = __half2float(__float2half_rn(v1));
            float h2 = __half2float(__float2half_rn(v2)), h3 = __half2float(__float2half_rn(v3));
            *reinterpret_cast<uint32_t*>(&gh[(size_t)row0 * DD + col])       = pack_half2(h0, h1);
            *reinterpret_cast<uint32_t*>(&gl[(size_t)row0 * DD + col])       = pack_half2(v0 - h0, v1 - h1);
            *reinterpret_cast<uint32_t*>(&gh[(size_t)(row0 + 8) * DD + col]) = pack_half2(h2, h3);
            *reinterpret_cast<uint32_t*>(&gl[(size_t)(row0 + 8) * DD + col]) = pack_half2(v2 - h2, v3 - h3);
        }
    } else {
        // ---- V: stage to smem, transpose, fp16 store ----
        const int lr = lane >> 2, lc = 2 * (lane & 3);
        #pragma unroll
        for (int np = 0; np < 8; np++) {
            #pragma unroll
            for (int nn = 0; nn < 2; nn++) {
                int c0 = np * 16 + nn * 8 + lc;
                float* p0 = tileC + (m0 + lr) * 132 + c0;
                float* p1 = tileC + (m0 + lr + 8) * 132 + c0;
                p0[0] = C[np * 2 + nn][0]; p0[1] = C[np * 2 + nn][1];
                p1[0] = C[np * 2 + nn][2]; p1[1] = C[np * 2 + nn][3];
            }
        }
        __syncthreads();
        const int od = t >> 1, seg = t & 1;
        #pragma unroll
        for (int j8 = 0; j8 < 8; j8++) {
            __align__(16) __half hs[8];
            #pragma unroll
            for (int j = 0; j < 8; j++)
                hs[j] = __float2half_rn(tileC[(seg * 64 + j8 * 8 + j) * 132 + od]);
            size_t ob = (size_t)(b * DD + od) * SS + s0 + seg * 64 + j8 * 8;
            *reinterpret_cast<uint4*>(&g_Vth[ob]) = *reinterpret_cast<uint4*>(hs);
        }
    }
}

// ---- flash v4 (R14 structure): fp16 3+1 passes; mbarrier pipeline ----
#define BQ 128
#define BK 64
#define QH_OFF 0
#define QL_OFF 32768
#define K_OFF  65536
#define KSTAGE 32768      /* [Kh 16K | Kl 16K] x2 */
#define V_OFF  131072
#define VSTAGE 16384      /* [Vh 16K] x4 */
#define RK_OFF 196608     /* 4 x 256 B */
#define MB_OFF 197632     /* fK0 fK1 eK0 eK1 | fV0..3 | eV0..3 */
#define FSMEM_TOTAL 197760
#define NT (SS / BK)

__global__ __launch_bounds__(256, 1) void flash_mma_kernel(float* __restrict__ outp) {
    extern __shared__ char smem[];
    const uint32_t sb = smem_u32(smem);
    const uint32_t mb = sb + MB_OFF;
    const int t = threadIdx.x, w = t >> 5, lane = t & 31;
    const int b = blockIdx.x >> 5, qt = blockIdx.x & 31;
    const int qtok = b * SS + qt * BQ;
    const int m0 = w * 16;
    const int g = lane >> 3, rr = lane & 7;
    const int rowA = m0 + ((g & 1) << 3) + rr;  const int hA = g >> 1;
    const int rowB8 = ((g >> 1) << 3) + rr;      const int hB = g & 1;

    if (t == 0) {
        #pragma unroll
        for (int i = 0; i < 12; i++) MBAR_INIT(mb + i * 8, 256);
    }

    auto produce = [&](int p) {
        const int s2 = p & 1;
        const int s4 = p & 3;
        if (p >= 2) MBAR_WAIT(mb + 16 + s2 * 8, ((p >> 1) - 1) & 1);     // empty_K
        if (p >= 4) MBAR_WAIT(mb + 64 + s4 * 8, ((p >> 2) - 1) & 1);     // empty_V
        const int ktok = b * SS + p * BK;
        const uint32_t kb = sb + K_OFF + (uint32_t)s2 * KSTAGE;
        if (t < 16) cpasync16(sb + RK_OFF + s4 * 256 + t * 16, g_rk + ktok + t * 4);
        #pragma unroll
        for (int it = 0; it < 4; it++) {
            int lin = t + it * 256;
            int kr = lin >> 4, kc = lin & 15;
            cpasync16(kb + sw256(kr, kc), g_Kh + (size_t)(ktok + kr) * DD + kc * 8);
            cpasync16(kb + 16384 + sw256(kr, kc), g_Kl + (size_t)(ktok + kr) * DD + kc * 8);
        }
        CPA_MBAR_ARRIVE(mb + s2 * 8);                                    // full_K (+rk)
        const uint32_t vb = sb + V_OFF + (uint32_t)s4 * VSTAGE;
        #pragma unroll
        for (int it = 0; it < 4; it++) {
            int lin = t + it * 256;
            int vr = lin >> 3, vc = lin & 7;
            cpasync16(vb + sw128(vr, vc), g_Vth + (size_t)(b * DD + vr) * SS + p * BK + vc * 8);
        }
        CPA_MBAR_ARRIVE(mb + 32 + s4 * 8);                               // full_V
    };

    produce(0);
    produce(1);

    #pragma unroll
    for (int it = 0; it < 8; it++) {
        int lin = t + it * 256, r = lin >> 4, c = lin & 15;
        *reinterpret_cast<uint4*>(smem + QH_OFF + sw256(r, c)) =
            *reinterpret_cast<const uint4*>(g_Qh + (size_t)(qtok + r) * DD + c * 8);
        *reinterpret_cast<uint4*>(smem + QL_OFF + sw256(r, c)) =
            *reinterpret_cast<const uint4*>(g_Ql + (size_t)(qtok + r) * DD + c * 8);
    }
    const int r0g = qtok + m0 + (lane >> 2);
    const float rq0 = g_rq[r0g], rq1 = g_rq[r0g + 8];

    float o[16][4];
    #pragma unroll
    for (int i = 0; i < 16; i++) { o[i][0] = o[i][1] = o[i][2] = o[i][3] = 0.f; }
    float mr0 = -INFINITY, mr1 = -INFINITY, lr0 = 0.f, lr1 = 0.f;

    __syncthreads();   // Q visible + mbarriers initialized

    for (int kt = 0; kt < NT; kt++) {
        const int s2 = kt & 1;
        const int s4 = kt & 3;
        const uint32_t kb = sb + K_OFF + (uint32_t)s2 * KSTAGE;
        const uint32_t vb = sb + V_OFF + (uint32_t)s4 * VSTAGE;
        const float* smk = (const float*)(smem + RK_OFF + s4 * 256);

        MBAR_WAIT(mb + s2 * 8, (kt >> 1) & 1);          // full_K (+rk)

        float S[8][4];
        #pragma unroll
        for (int i = 0; i < 8; i++) { S[i][0] = S[i][1] = S[i][2] = S[i][3] = 0.f; }
        #pragma unroll
        for (int kc = 0; kc < 8; kc++) {
            uint32_t Ah[4], Al[4];
            ldsm4(Ah, sb + QH_OFF + sw256(rowA, kc * 2 + hA));
            ldsm4(Al, sb + QL_OFF + sw256(rowA, kc * 2 + hA));
            #pragma unroll
            for (int np = 0; np < 4; np++) {
                uint32_t Bh[4], Bl[4];
                ldsm4(Bh, kb + sw256(np * 16 + rowB8, kc * 2 + hB));
                ldsm4(Bl, kb + 16384 + sw256(np * 16 + rowB8, kc * 2 + hB));
                mma16816h(S[2 * np], Ah, Bh);     mma16816h(S[2 * np + 1], Ah, Bh + 2);
                mma16816h(S[2 * np], Ah, Bl);     mma16816h(S[2 * np + 1], Ah, Bl + 2);
                mma16816h(S[2 * np], Al, Bh);     mma16816h(S[2 * np + 1], Al, Bh + 2);
            }
        }
        MBAR_ARRIVE(mb + 16 + s2 * 8);                  // empty_K

        const int cbase = 2 * (lane & 3);
        float tm0 = -INFINITY, tm1 = -INFINITY;
        #pragma unroll
        for (int nt = 0; nt < 8; nt++) {
            float2 mk2 = *reinterpret_cast<const float2*>(&smk[nt * 8 + cbase]);
            S[nt][0] += rq0 * mk2.x; S[nt][1] += rq0 * mk2.y;
            S[nt][2] += rq1 * mk2.x; S[nt][3] += rq1 * mk2.y;
            tm0 = fmaxf(tm0, fmaxf(S[nt][0], S[nt][1]));
            tm1 = fmaxf(tm1, fmaxf(S[nt][2], S[nt][3]));
        }
        tm0 = fmaxf(tm0, __shfl_xor_sync(0xFFFFFFFFu, tm0, 1));
        tm0 = fmaxf(tm0, __shfl_xor_sync(0xFFFFFFFFu, tm0, 2));
        tm1 = fmaxf(tm1, __shfl_xor_sync(0xFFFFFFFFu, tm1, 1));
        tm1 = fmaxf(tm1, __shfl_xor_sync(0xFFFFFFFFu, tm1, 2));
        float nm0 = fmaxf(mr0, tm0), nm1 = fmaxf(mr1, tm1);
        float al0 = __expf(mr0 - nm0), al1 = __expf(mr1 - nm1);
        mr0 = nm0; mr1 = nm1;

        uint32_t PhL[8], PhH[8];
        float s0 = 0.f, s1 = 0.f;
        #pragma unroll
        for (int nt = 0; nt < 8; nt++) {
            float p0 = __expf(S[nt][0] - nm0), p1 = __expf(S[nt][1] - nm0);
            float p2 = __expf(S[nt][2] - nm1), p3 = __expf(S[nt][3] - nm1);
            s0 += p0 + p1; s1 += p2 + p3;
            PhL[nt] = pack_half2(p0, p1);
            PhH[nt] = pack_half2(p2, p3);
        }
        s0 += __shfl_xor_sync(0xFFFFFFFFu, s0, 1);
        s0 += __shfl_xor_sync(0xFFFFFFFFu, s0, 2);
        s1 += __shfl_xor_sync(0xFFFFFFFFu, s1, 1);
        s1 += __shfl_xor_sync(0xFFFFFFFFu, s1, 2);
        lr0 = lr0 * al0 + s0; lr1 = lr1 * al1 + s1;
        if (al0 != 1.f || al1 != 1.f) {
            #pragma unroll
            for (int i = 0; i < 16; i++) { o[i][0] *= al0; o[i][1] *= al0; o[i][2] *= al1; o[i][3] *= al1; }
        }

        MBAR_WAIT(mb + 32 + s4 * 8, (kt >> 2) & 1);     // full_V

        #pragma unroll
        for (int kc = 0; kc < 4; kc++) {
            uint32_t Aph[4] = {PhL[2 * kc], PhH[2 * kc], PhL[2 * kc + 1], PhH[2 * kc + 1]};
            #pragma unroll
            for (int dp = 0; dp < 8; dp++) {
                uint32_t Bh[4];
                ldsm4(Bh, vb + sw128(dp * 16 + rowB8, kc * 2 + hB));
                mma16816h(o[2 * dp], Aph, Bh);
                mma16816h(o[2 * dp + 1], Aph, Bh + 2);
            }
        }
        MBAR_ARRIVE(mb + 64 + s4 * 8);                  // empty_V (+rk)

        if (kt + 2 < NT) produce(kt + 2);
    }

    const float inv0 = 1.f / lr0, inv1 = 1.f / lr1;
    #pragma unroll
    for (int nt = 0; nt < 16; nt++) {
        int col = nt * 8 + 2 * (lane & 3);
        *reinterpret_cast<float2*>(outp + (size_t)r0g * DD + col) =
            make_float2(o[nt][0] * inv0, o[nt][1] * inv0);
        *reinterpret_cast<float2*>(outp + (size_t)(r0g + 8) * DD + col) =
            make_float2(o[nt][2] * inv1, o[nt][3] * inv1);
    }
}

extern "C" void kernel_launch(void* const* d_in, const int* in_sizes, int n_in,
                              void* d_out, int out_size) {
    const float* x  = (const float*)d_in[0];
    const float* wq = (const float*)d_in[2];
    const float* wk = (const float*)d_in[3];
    const float* wv = (const float*)d_in[4];
    float* out = (float*)d_out;

    cudaFuncSetAttribute(proj_kernel, cudaFuncAttributeMaxDynamicSharedMemorySize, PSMEM);
    cudaFuncSetAttribute(flash_mma_kernel, cudaFuncAttributeMaxDynamicSharedMemorySize, FSMEM_TOTAL);

    proj_kernel<<<dim3(128, 3), 256, PSMEM>>>(x, wq, wk, wv);
    flash_mma_kernel<<<BB * (SS / BQ), 256, FSMEM_TOTAL>>>(out);
}